// round 12
// baseline (speedup 1.0000x reference)
#include <cuda_runtime.h>
#include <cuda_fp16.h>
#include <cstdint>

#define H 768
#define HEADS 8
#define T_STEPS 3
#define B 128
#define N_ATOM 48
#define NPG 49
#define EPG 144
#define NN (B*NPG)        // 6272 nodes
#define EE (B*EPG)        // 18432 edges
#define HH (HEADS*H)      // 6144
#define NH2 (2*HH)        // 12288 combined fs|fd columns
#define G3H (3*H)         // 2304

// ---------------- scratch (__device__ globals; no allocation) ----------------
__device__ __half   g_f[(size_t)NN*NH2];      // combined [fs | fd] per node, fp16
__device__ float    g_logits[EE*HEADS];
__device__ float    g_att[EE*HEADS];
__device__ float    g_mol[B*H];
__device__ float    g_x[B*H];
__device__ float    g_gi[B*G3H];
__device__ float    g_gh[B*G3H];
__device__ float    g_bias2[NH2];
// fp16 buffers
__device__ __half g_ah[(size_t)NN*H];
__device__ __half g_wh[(size_t)NH2*H];   // [12288][768] transposed weights fp16
// CSR
__device__ int g_offA[NN];
__device__ int g_degA[NN];
__device__ int g_eix[EE];

// ---------------- PTX helpers ----------------
__device__ __forceinline__ uint32_t smem_u32(const void* p) {
    uint32_t a;
    asm("{ .reg .u64 t; cvta.to.shared.u64 t, %1; cvt.u32.u64 %0, t; }" : "=r"(a) : "l"(p));
    return a;
}
__device__ __forceinline__ void cp16(uint32_t saddr, const void* gptr) {
    asm volatile("cp.async.cg.shared.global [%0], [%1], 16;" :: "r"(saddr), "l"(gptr));
}
__device__ __forceinline__ void cp_commit() { asm volatile("cp.async.commit_group;"); }
__device__ __forceinline__ void cp_wait2() { asm volatile("cp.async.wait_group 2;"); }
__device__ __forceinline__ void cp_wait1() { asm volatile("cp.async.wait_group 1;"); }
__device__ __forceinline__ void cp_wait0() { asm volatile("cp.async.wait_group 0;"); }
__device__ __forceinline__ void ldm_x4(uint32_t* r, uint32_t addr) {
    asm volatile("ldmatrix.sync.aligned.m8n8.x4.shared.b16 {%0,%1,%2,%3}, [%4];"
                 : "=r"(r[0]), "=r"(r[1]), "=r"(r[2]), "=r"(r[3]) : "r"(addr));
}
__device__ __forceinline__ void mma_f16(float* c, const uint32_t* a, const uint32_t* b) {
    asm volatile(
        "mma.sync.aligned.m16n8k16.row.col.f32.f16.f16.f32 "
        "{%0,%1,%2,%3}, {%4,%5,%6,%7}, {%8,%9}, {%0,%1,%2,%3};"
        : "+f"(c[0]), "+f"(c[1]), "+f"(c[2]), "+f"(c[3])
        : "r"(a[0]), "r"(a[1]), "r"(a[2]), "r"(a[3]), "r"(b[0]), "r"(b[1]));
}

// ---------------- single-pass fp16 HMMA GEMM, wide-N tile ----------------
// f[NN,12288] = Ah[NN,768] @ Wh^T + bias2 ; W stored [12288][768] K-major fp16
#define GM 128
#define GN 256
#define GK 32
#define KCH (H/GK)       // 24
#define NSTG 4
#define ST_SZ 24576      // A 8K | B 16K
#define OFF_A 0
#define OFF_B 8192
#define TC_SMEM (NSTG*ST_SZ)   // 96KB

__global__ __launch_bounds__(256, 1) void hmma_gemm(
    const __half* __restrict__ Ah, const __half* __restrict__ Wh,
    const float* __restrict__ bias, __half* __restrict__ C)
{
    extern __shared__ char smem[];
    const uint32_t sb = smem_u32(smem);
    const int tid = threadIdx.x;
    const int wid = tid >> 5, lane = tid & 31;
    const int wm = wid >> 2, wn = wid & 3;        // 2 x 4 warps -> 64 x 64 per warp
    const int m0 = blockIdx.y * GM, n0 = blockIdx.x * GN;

    const char* aP = (const char*)(Ah + (size_t)m0 * H);
    const char* bP = (const char*)(Wh + (size_t)n0 * H);

    float acc[4][8][4];
    #pragma unroll
    for (int i = 0; i < 4; i++)
        #pragma unroll
        for (int j = 0; j < 8; j++)
            #pragma unroll
            for (int q = 0; q < 4; q++) acc[i][j][q] = 0.f;

    // stage loader: A 512 chunks (2 iters) + B 1024 chunks (4 iters), 16B each
    auto load_stage = [&](int stage, int chunk) {
        uint32_t st = sb + stage * ST_SZ;
        int kb = chunk * 64;
        #pragma unroll
        for (int i = 0; i < 2; i++) {
            int cid = (i << 8) + tid;            // 0..511
            int row = cid >> 2, ch = cid & 3;
            uint32_t off = OFF_A + row * 64 + (((ch ^ ((row >> 1) & 3))) << 4);
            cp16(st + off, aP + (size_t)row * (H*2) + kb + ch * 16);
        }
        #pragma unroll
        for (int i = 0; i < 4; i++) {
            int cid = (i << 8) + tid;            // 0..1023
            int row = cid >> 2, ch = cid & 3;
            uint32_t off = OFF_B + row * 64 + (((ch ^ ((row >> 1) & 3))) << 4);
            cp16(st + off, bP + (size_t)row * (H*2) + kb + ch * 16);
        }
        cp_commit();
    };

    load_stage(0, 0);
    load_stage(1, 1);
    load_stage(2, 2);

    const int arow = lane & 15;
    const int akh  = lane >> 4;          // 0/1 k-half
    const int bgrp = lane >> 3;          // 0..3: (nt-parity, k-half)
    const int brow8 = lane & 7;

    for (int c = 0; c < KCH; c++) {
        if (c < KCH-2) cp_wait2(); else if (c == KCH-2) cp_wait1(); else cp_wait0();
        __syncthreads();
        if (c + 3 < KCH) load_stage((c + 3) % NSTG, c + 3);

        uint32_t st = sb + (c % NSTG) * ST_SZ;
        #pragma unroll
        for (int j = 0; j < 2; j++) {            // two k16 steps per chunk
            uint32_t ah[4][4];
            int ka = j * 2 + akh;
            #pragma unroll
            for (int mt = 0; mt < 4; mt++) {
                int row = wm * 64 + mt * 16 + arow;
                uint32_t off = OFF_A + row * 64 + ((ka ^ ((row >> 1) & 3)) << 4);
                ldm_x4(ah[mt], st + off);
            }
            #pragma unroll
            for (int ntp = 0; ntp < 8; ntp += 2) {
                // x4: lanes 0-7 -> nt even khalf0, 8-15 -> nt even khalf1,
                //     16-23 -> nt odd khalf0, 24-31 -> nt odd khalf1
                uint32_t bq[4];
                int row = wn * 64 + (ntp + (bgrp >> 1)) * 8 + brow8;
                int ch = j * 2 + (bgrp & 1);
                uint32_t off = OFF_B + row * 64 + ((ch ^ ((row >> 1) & 3)) << 4);
                ldm_x4(bq, st + off);
                #pragma unroll
                for (int mt = 0; mt < 4; mt++) {
                    mma_f16(acc[mt][ntp],     ah[mt], bq);
                    mma_f16(acc[mt][ntp + 1], ah[mt], bq + 2);
                }
            }
        }
    }

    const int g = lane >> 2, tq = lane & 3;
    #pragma unroll
    for (int mt = 0; mt < 4; mt++) {
        #pragma unroll
        for (int nt = 0; nt < 8; nt++) {
            int row = m0 + wm*64 + mt*16 + g;
            int col = n0 + wn*64 + nt*8 + tq*2;
            float b0 = bias[col], b1 = bias[col + 1];
            __half2 v0 = __floats2half2_rn(acc[mt][nt][0] + b0, acc[mt][nt][1] + b1);
            __half2 v1 = __floats2half2_rn(acc[mt][nt][2] + b0, acc[mt][nt][3] + b1);
            *(__half2*)&C[(size_t)row * NH2 + col] = v0;
            *(__half2*)&C[(size_t)(row + 8) * NH2 + col] = v1;
        }
    }
}

// ---------------- conversions ----------------
__global__ void k_halfA(const float* __restrict__ in, __half* __restrict__ o, int n)
{
    int i = blockIdx.x * blockDim.x + threadIdx.x;
    if (i < n) o[i] = __float2half_rn(in[i]);
}

__global__ void k_halfWT2(const float* __restrict__ Ws, const float* __restrict__ Wd,
                          __half* __restrict__ WT)
{
    __shared__ float tile[32][33];
    int bx = blockIdx.x;
    const int half_nb = HH/32;
    const float* W = (bx < half_nb) ? Ws : Wd;
    int rowoff = (bx < half_nb) ? 0 : HH;
    int n0 = ((bx < half_nb) ? bx : bx - half_nb) * 32;
    int k0 = blockIdx.y * 32;
    int tx = threadIdx.x, ty = threadIdx.y;
    #pragma unroll
    for (int i = ty; i < 32; i += 8)
        tile[i][tx] = W[(size_t)(k0 + i) * HH + n0 + tx];
    __syncthreads();
    #pragma unroll
    for (int i = ty; i < 32; i += 8)
        WT[(size_t)(rowoff + n0 + i) * H + k0 + tx] = __float2half_rn(tile[tx][i]);
}

__global__ void k_bias2(const float* __restrict__ bs, const float* __restrict__ bd,
                        float* __restrict__ b2)
{
    int i = blockIdx.x * blockDim.x + threadIdx.x;
    if (i < HH) b2[i] = bs[i];
    else if (i < NH2) b2[i] = bd[i - HH];
}

__global__ void k_copy(float* d, const float* s, int n){ int i = blockIdx.x*blockDim.x + threadIdx.x; if (i < n) d[i] = s[i]; }

// ---------------- CSR build (per graph; deterministic) ----------------
__global__ void k_csr(const int* __restrict__ dst, int* __restrict__ offA,
                      int* __restrict__ degA, int* __restrict__ eix)
{
    __shared__ int cnt[NPG];
    __shared__ int basep[NPG];
    int g = blockIdx.x, tid = threadIdx.x;
    if (tid < NPG) cnt[tid] = 0;
    __syncthreads();
    if (tid < EPG) {
        int e = g * EPG + tid;
        atomicAdd(&cnt[dst[e] - g * NPG], 1);
    }
    __syncthreads();
    if (tid == 0) {
        int run = g * EPG;
        for (int i = 0; i < NPG; i++) {
            basep[i] = run;
            offA[g * NPG + i] = run;
            degA[g * NPG + i] = cnt[i];
            run += cnt[i];
        }
        for (int j = 0; j < EPG; j++) {
            int e = g * EPG + j;
            int dl = dst[e] - g * NPG;
            eix[basep[dl]++] = e;
        }
    }
}

// ---------------- edge kernels ----------------
__global__ __launch_bounds__(256) void k_logits(const __half* __restrict__ f,
                                                const float* __restrict__ attn_a,
                                                const int* __restrict__ src,
                                                const int* __restrict__ dst,
                                                float* __restrict__ logits)
{
    int e = blockIdx.x;
    int h = threadIdx.x >> 5;
    int lane = threadIdx.x & 31;
    int s = src[e], d = dst[e];
    const __half2* pf = (const __half2*)(f + (size_t)s*NH2 + h*H);
    const __half2* pd = (const __half2*)(f + (size_t)d*NH2 + HH + h*H);
    const float2* pa = (const float2*)(attn_a + h*H);
    float acc = 0.f;
    #pragma unroll
    for (int i = lane; i < H/2; i += 32) {
        float2 a = __half22float2(pf[i]);
        float2 b = __half22float2(pd[i]);
        float2 w = pa[i];
        float v;
        v = a.x + b.x; v = v > 0.f ? v : 0.2f*v; acc += v * w.x;
        v = a.y + b.y; v = v > 0.f ? v : 0.2f*v; acc += v * w.y;
    }
    #pragma unroll
    for (int o = 16; o; o >>= 1) acc += __shfl_xor_sync(0xffffffffu, acc, o);
    if (lane == 0) logits[e*HEADS + h] = acc;
}

__global__ __launch_bounds__(256) void k_softmax(const float* __restrict__ logits,
                                                 const int* __restrict__ offA,
                                                 const int* __restrict__ degA,
                                                 const int* __restrict__ eix,
                                                 float* __restrict__ att)
{
    int n = blockIdx.x * 8 + (threadIdx.x >> 5);
    int lane = threadIdx.x & 31;
    int off = offA[n], deg = degA[n];
    int h = lane & 7, grp = lane >> 3;
    float m = -1e30f;
    for (int j = grp; j < deg; j += 4)
        m = fmaxf(m, logits[eix[off + j]*HEADS + h]);
    m = fmaxf(m, __shfl_xor_sync(0xffffffffu, m, 8));
    m = fmaxf(m, __shfl_xor_sync(0xffffffffu, m, 16));
    float s = 0.f;
    for (int j = grp; j < deg; j += 4)
        s += expf(logits[eix[off + j]*HEADS + h] - m);
    s += __shfl_xor_sync(0xffffffffu, s, 8);
    s += __shfl_xor_sync(0xffffffffu, s, 16);
    float inv = 1.f / s;
    for (int j = grp; j < deg; j += 4) {
        int ei = eix[off + j];
        att[ei*HEADS + h] = expf(logits[ei*HEADS + h] - m) * inv;
    }
}

// block per node; outputs fp16 ah (next GEMM A) + GRU input x (virtual nodes)
__global__ __launch_bounds__(256) void k_aggregate(const float* __restrict__ att,
                                                   const __half* __restrict__ f,
                                                   const int* __restrict__ src,
                                                   const int* __restrict__ offA,
                                                   const int* __restrict__ degA,
                                                   const int* __restrict__ eix,
                                                   __half* __restrict__ ah,
                                                   float* __restrict__ x)
{
    __shared__ float coef[96*HEADS];
    __shared__ int   srcs[96];
    int n = blockIdx.x, tid = threadIdx.x;
    int off = offA[n], deg = degA[n];
    int g = n / NPG, nl = n - g * NPG;
    for (int idx = tid; idx < deg*HEADS; idx += 256) {
        int j = idx >> 3, h = idx & 7;
        coef[idx] = att[eix[off + j]*HEADS + h] * 0.125f;
    }
    if (tid < deg) srcs[tid] = src[eix[off + tid]];
    __syncthreads();
    #pragma unroll
    for (int i = tid; i < H; i += 256) {
        float v = 0.f;
        for (int j = 0; j < deg; j++) {
            const __half* p = f + (size_t)srcs[j]*NH2 + i;
            const float* cj = coef + j*HEADS;
            #pragma unroll
            for (int h = 0; h < HEADS; h++) v += cj[h] * __half2float(p[h*H]);
        }
        size_t o = (size_t)n*H + i;
        ah[o] = __float2half_rn(v);
        if (nl == NPG - 1) x[g*H + i] = v;
    }
}

__global__ void k_attn_out(const float* __restrict__ att, const int* __restrict__ eids,
                           float* __restrict__ out)
{
    int i = blockIdx.x*blockDim.x + threadIdx.x;
    if (i >= B*N_ATOM) return;
    int e = eids[i];
    float s = 0.f;
    #pragma unroll
    for (int h = 0; h < HEADS; h++) s += att[e*HEADS + h];
    out[i] = s * 0.125f;
}

// ---------------- batched NT SGEMM for GRU ----------------
#define BM 128
#define BN 128
#define BK 8
__global__ __launch_bounds__(256) void sgemm_nt2(
    const float* __restrict__ A0, const float* __restrict__ W0, const float* __restrict__ b0,
    float* __restrict__ C0,
    const float* __restrict__ A1, const float* __restrict__ W1, const float* __restrict__ b1,
    float* __restrict__ C1,
    int M, int N, int K)
{
    __shared__ float As[BK][BM];
    __shared__ float Bs[BK][BN];
    const float* A    = blockIdx.z ? A1 : A0;
    const float* W    = blockIdx.z ? W1 : W0;
    const float* bias = blockIdx.z ? b1 : b0;
    float*       C    = blockIdx.z ? C1 : C0;
    const int bx = blockIdx.x, by = blockIdx.y;
    const int tid = threadIdx.x;
    const int tx = tid & 15, ty = tid >> 4;
    const float* Ap = A + (size_t)by*BM*K;
    const float* Wp = W + (size_t)bx*BN*K;
    const int aRow = tid >> 1, aCol4 = (tid & 1) * 4;
    float acc[8][8];
    #pragma unroll
    for (int i = 0; i < 8; i++)
        #pragma unroll
        for (int j = 0; j < 8; j++) acc[i][j] = 0.f;
    for (int k0 = 0; k0 < K; k0 += BK) {
        float4 av = *(const float4*)(Ap + (size_t)aRow*K + k0 + aCol4);
        As[aCol4+0][aRow] = av.x; As[aCol4+1][aRow] = av.y;
        As[aCol4+2][aRow] = av.z; As[aCol4+3][aRow] = av.w;
        float4 wv = *(const float4*)(Wp + (size_t)aRow*K + k0 + aCol4);
        Bs[aCol4+0][aRow] = wv.x; Bs[aCol4+1][aRow] = wv.y;
        Bs[aCol4+2][aRow] = wv.z; Bs[aCol4+3][aRow] = wv.w;
        __syncthreads();
        #pragma unroll
        for (int k = 0; k < BK; k++) {
            float a[8], b[8];
            #pragma unroll
            for (int i = 0; i < 8; i++) a[i] = As[k][ty*8 + i];
            #pragma unroll
            for (int j = 0; j < 8; j++) b[j] = Bs[k][tx*8 + j];
            #pragma unroll
            for (int i = 0; i < 8; i++)
                #pragma unroll
                for (int j = 0; j < 8; j++)
                    acc[i][j] += a[i] * b[j];
        }
        __syncthreads();
    }
    #pragma unroll
    for (int i = 0; i < 8; i++) {
        int row = by*BM + ty*8 + i;
        #pragma unroll
        for (int j = 0; j < 8; j++) {
            int col = bx*BN + tx*8 + j;
            C[(size_t)row*N + col] = acc[i][j] + bias[col];
        }
    }
}

__global__ void k_gru(const float* __restrict__ gi, const float* __restrict__ gh,
                      float* __restrict__ mol, float* __restrict__ out_final)
{
    int i = blockIdx.x*blockDim.x + threadIdx.x;
    if (i >= B*H) return;
    int b = i / H, d = i - b*H;
    float ir = gi[b*G3H + d],       hr = gh[b*G3H + d];
    float iz = gi[b*G3H + H + d],   hz = gh[b*G3H + H + d];
    float in_= gi[b*G3H + 2*H + d], hn = gh[b*G3H + 2*H + d];
    float r = 1.f / (1.f + expf(-(ir + hr)));
    float z = 1.f / (1.f + expf(-(iz + hz)));
    float n = tanhf(in_ + r * hn);
    float hp = mol[i];
    float v = (1.f - z) * n + z * hp;
    v = v > 0.f ? v : 0.f;
    mol[i] = v;
    if (out_final) out_final[i] = v;
}

// ---------------- host ----------------
extern "C" void kernel_launch(void* const* d_in, const int* in_sizes, int n_in,
                              void* d_out, int out_size)
{
    const float* h_nodes  = (const float*)d_in[0];
    const float* mol_feat = (const float*)d_in[1];
    const float* W_src    = (const float*)d_in[2];
    const float* b_src    = (const float*)d_in[3];
    const float* W_dst    = (const float*)d_in[4];
    const float* b_dst    = (const float*)d_in[5];
    const float* attn_a   = (const float*)d_in[6];
    const float* W_ih     = (const float*)d_in[7];
    const float* W_hh     = (const float*)d_in[8];
    const float* b_ih     = (const float*)d_in[9];
    const float* b_hh     = (const float*)d_in[10];
    const int*   src      = (const int*)d_in[11];
    const int*   dst      = (const int*)d_in[12];
    const int*   vnids    = (const int*)d_in[13];  (void)vnids;
    const int*   eids     = (const int*)d_in[14];
    float* out = (float*)d_out;

    float *logits, *att, *mol, *x, *gi, *gh, *bias2;
    __half *f, *ah, *wh;
    int *offA, *degA, *eixp;
    cudaGetSymbolAddress((void**)&f,      g_f);
    cudaGetSymbolAddress((void**)&logits, g_logits);
    cudaGetSymbolAddress((void**)&att,    g_att);
    cudaGetSymbolAddress((void**)&mol,    g_mol);
    cudaGetSymbolAddress((void**)&x,      g_x);
    cudaGetSymbolAddress((void**)&gi,     g_gi);
    cudaGetSymbolAddress((void**)&gh,     g_gh);
    cudaGetSymbolAddress((void**)&bias2,  g_bias2);
    cudaGetSymbolAddress((void**)&ah,     g_ah);
    cudaGetSymbolAddress((void**)&wh,     g_wh);
    cudaGetSymbolAddress((void**)&offA,   g_offA);
    cudaGetSymbolAddress((void**)&degA,   g_degA);
    cudaGetSymbolAddress((void**)&eixp,   g_eix);

    cudaFuncSetAttribute(hmma_gemm, cudaFuncAttributeMaxDynamicSharedMemorySize, TC_SMEM);

    k_copy<<<(B*H + 255)/256, 256>>>(mol, mol_feat, B*H);
    k_csr<<<B, 160>>>(dst, offA, degA, eixp);
    k_halfA<<<(NN*H + 255)/256, 256>>>(h_nodes, ah, NN*H);

    for (int t = 0; t < T_STEPS; t++) {
        k_bias2<<<(NH2 + 255)/256, 256>>>(b_src + t*HH, b_dst + t*HH, bias2);
        k_halfWT2<<<dim3(2*HH/32, H/32), dim3(32, 8)>>>(
            W_src + (size_t)t*H*HH, W_dst + (size_t)t*H*HH, wh);

        dim3 gg(NH2/GN, NN/GM);   // 48 x 49
        hmma_gemm<<<gg, 256, TC_SMEM>>>(ah, wh, bias2, f);

        k_logits<<<EE, 256>>>(f, attn_a + (size_t)t*HEADS*H, src, dst, logits);
        k_softmax<<<NN/8, 256>>>(logits, offA, degA, eixp, att);
        k_aggregate<<<NN, 256>>>(att, f, src, offA, degA, eixp, ah, x);
        k_attn_out<<<(B*N_ATOM + 255)/256, 256>>>(att, eids, out + B*H + t*B*N_ATOM);

        sgemm_nt2<<<dim3(G3H/BN, B/BM, 2), 256>>>(
            x,   W_ih + (size_t)t*G3H*H, b_ih + t*G3H, gi,
            mol, W_hh + (size_t)t*G3H*H, b_hh + t*G3H, gh,
            B, G3H, H);
        k_gru<<<(B*H + 255)/256, 256>>>(gi, gh, mol, (t == T_STEPS-1) ? out : nullptr);
    }
}

// round 13
// speedup vs baseline: 1.1062x; 1.1062x over previous
#include <cuda_runtime.h>
#include <cuda_fp16.h>
#include <cstdint>

#define H 768
#define HEADS 8
#define T_STEPS 3
#define B 128
#define N_ATOM 48
#define NPG 49
#define EPG 144
#define NN (B*NPG)        // 6272 nodes
#define EE (B*EPG)        // 18432 edges
#define HH (HEADS*H)      // 6144
#define NH2 (2*HH)        // 12288 combined fs|fd columns
#define G3H (3*H)         // 2304

// ---------------- scratch (__device__ globals; no allocation) ----------------
__device__ __half   g_f[(size_t)NN*NH2];      // combined [fs | fd] per node, fp16
__device__ float    g_logits[EE*HEADS];
__device__ float    g_att[EE*HEADS];
__device__ float    g_mol[B*H];
__device__ float    g_x[B*H];
__device__ float    g_gi[B*G3H];
__device__ float    g_gh[B*G3H];
__device__ float    g_bias2[NH2];
// fp16 buffers
__device__ __half g_ah[(size_t)NN*H];
__device__ __half g_wh[(size_t)NH2*H];   // [12288][768] transposed weights fp16
// CSR
__device__ int g_offA[NN];
__device__ int g_degA[NN];
__device__ int g_eix[EE];

// ---------------- PTX helpers ----------------
__device__ __forceinline__ uint32_t smem_u32(const void* p) {
    uint32_t a;
    asm("{ .reg .u64 t; cvta.to.shared.u64 t, %1; cvt.u32.u64 %0, t; }" : "=r"(a) : "l"(p));
    return a;
}
__device__ __forceinline__ void cp16(uint32_t saddr, const void* gptr) {
    asm volatile("cp.async.cg.shared.global [%0], [%1], 16;" :: "r"(saddr), "l"(gptr));
}
__device__ __forceinline__ void cp_commit() { asm volatile("cp.async.commit_group;"); }
__device__ __forceinline__ void cp_wait2() { asm volatile("cp.async.wait_group 2;"); }
__device__ __forceinline__ void cp_wait1() { asm volatile("cp.async.wait_group 1;"); }
__device__ __forceinline__ void cp_wait0() { asm volatile("cp.async.wait_group 0;"); }
__device__ __forceinline__ void ldm_x4(uint32_t* r, uint32_t addr) {
    asm volatile("ldmatrix.sync.aligned.m8n8.x4.shared.b16 {%0,%1,%2,%3}, [%4];"
                 : "=r"(r[0]), "=r"(r[1]), "=r"(r[2]), "=r"(r[3]) : "r"(addr));
}
__device__ __forceinline__ void ldm_x2(uint32_t* r, uint32_t addr) {
    asm volatile("ldmatrix.sync.aligned.m8n8.x2.shared.b16 {%0,%1}, [%2];"
                 : "=r"(r[0]), "=r"(r[1]) : "r"(addr));
}
__device__ __forceinline__ void mma_f16(float* c, const uint32_t* a, const uint32_t* b) {
    asm volatile(
        "mma.sync.aligned.m16n8k16.row.col.f32.f16.f16.f32 "
        "{%0,%1,%2,%3}, {%4,%5,%6,%7}, {%8,%9}, {%0,%1,%2,%3};"
        : "+f"(c[0]), "+f"(c[1]), "+f"(c[2]), "+f"(c[3])
        : "r"(a[0]), "r"(a[1]), "r"(a[2]), "r"(a[3]), "r"(b[0]), "r"(b[1]));
}

// ---------------- single-pass fp16 HMMA GEMM (R11 config) ----------------
#define GM 128
#define GN 128
#define GK 32
#define KCH (H/GK)       // 24
#define NSTG 4
#define ST_SZ 16384      // A 8K | B 8K
#define OFF_A 0
#define OFF_B 8192
#define TC_SMEM (NSTG*ST_SZ)   // 64KB

__global__ __launch_bounds__(256, 2) void hmma_gemm(
    const __half* __restrict__ Ah, const __half* __restrict__ Wh,
    const float* __restrict__ bias, __half* __restrict__ C)
{
    extern __shared__ char smem[];
    const uint32_t sb = smem_u32(smem);
    const int tid = threadIdx.x;
    const int wid = tid >> 5, lane = tid & 31;
    const int wm = wid >> 2, wn = wid & 3;
    const int m0 = blockIdx.y * GM, n0 = blockIdx.x * GN;

    const char* aP = (const char*)(Ah + (size_t)m0 * H);
    const char* bP = (const char*)(Wh + (size_t)n0 * H);

    float acc[4][4][4];
    #pragma unroll
    for (int i = 0; i < 4; i++)
        #pragma unroll
        for (int j = 0; j < 4; j++)
            #pragma unroll
            for (int q = 0; q < 4; q++) acc[i][j][q] = 0.f;

    auto load_stage = [&](int stage, int chunk) {
        uint32_t st = sb + stage * ST_SZ;
        int kb = chunk * 64;
        #pragma unroll
        for (int i = 0; i < 4; i++) {
            int buf = i >> 1;
            int rem = ((i & 1) << 8) + tid;
            int row = rem >> 2, ch = rem & 3;
            uint32_t off = (uint32_t)buf * 8192 + row * 64 + (((ch ^ ((row >> 1) & 3))) << 4);
            const char* base = (buf == 0) ? aP : bP;
            cp16(st + off, base + (size_t)row * (H*2) + kb + ch * 16);
        }
        cp_commit();
    };

    load_stage(0, 0);
    load_stage(1, 1);
    load_stage(2, 2);

    const int arow = lane & 15;
    const int akh  = lane >> 4;
    const int brow = lane & 7;
    const int bkh  = (lane >> 3) & 1;

    for (int c = 0; c < KCH; c++) {
        if (c < KCH-2) cp_wait2(); else if (c == KCH-2) cp_wait1(); else cp_wait0();
        __syncthreads();
        if (c + 3 < KCH) load_stage((c + 3) % NSTG, c + 3);

        uint32_t st = sb + (c % NSTG) * ST_SZ;
        #pragma unroll
        for (int j = 0; j < 2; j++) {
            uint32_t ah[4][4];
            int ka = j * 2 + akh;
            #pragma unroll
            for (int mt = 0; mt < 4; mt++) {
                int row = wm * 64 + mt * 16 + arow;
                uint32_t off = row * 64 + ((ka ^ ((row >> 1) & 3)) << 4);
                ldm_x4(ah[mt], st + OFF_A + off);
            }
            int kb2 = j * 2 + bkh;
            #pragma unroll
            for (int nt = 0; nt < 4; nt++) {
                uint32_t bh[2];
                int row = wn * 32 + nt * 8 + brow;
                uint32_t off = row * 64 + ((kb2 ^ ((row >> 1) & 3)) << 4);
                ldm_x2(bh, st + OFF_B + off);
                #pragma unroll
                for (int mt = 0; mt < 4; mt++)
                    mma_f16(acc[mt][nt], ah[mt], bh);
            }
        }
    }

    const int g = lane >> 2, tq = lane & 3;
    #pragma unroll
    for (int mt = 0; mt < 4; mt++) {
        #pragma unroll
        for (int nt = 0; nt < 4; nt++) {
            int row = m0 + wm*64 + mt*16 + g;
            int col = n0 + wn*32 + nt*8 + tq*2;
            float b0 = bias[col], b1 = bias[col + 1];
            __half2 v0 = __floats2half2_rn(acc[mt][nt][0] + b0, acc[mt][nt][1] + b1);
            __half2 v1 = __floats2half2_rn(acc[mt][nt][2] + b0, acc[mt][nt][3] + b1);
            *(__half2*)&C[(size_t)row * NH2 + col] = v0;
            *(__half2*)&C[(size_t)(row + 8) * NH2 + col] = v1;
        }
    }
}

// ---------------- conversions ----------------
__global__ void k_halfA(const float* __restrict__ in, __half* __restrict__ o, int n)
{
    int i = blockIdx.x * blockDim.x + threadIdx.x;
    if (i < n) o[i] = __float2half_rn(in[i]);
}

__global__ void k_halfWT2(const float* __restrict__ Ws, const float* __restrict__ Wd,
                          __half* __restrict__ WT)
{
    __shared__ float tile[32][33];
    int bx = blockIdx.x;
    const int half_nb = HH/32;
    const float* W = (bx < half_nb) ? Ws : Wd;
    int rowoff = (bx < half_nb) ? 0 : HH;
    int n0 = ((bx < half_nb) ? bx : bx - half_nb) * 32;
    int k0 = blockIdx.y * 32;
    int tx = threadIdx.x, ty = threadIdx.y;
    #pragma unroll
    for (int i = ty; i < 32; i += 8)
        tile[i][tx] = W[(size_t)(k0 + i) * HH + n0 + tx];
    __syncthreads();
    #pragma unroll
    for (int i = ty; i < 32; i += 8)
        WT[(size_t)(rowoff + n0 + i) * H + k0 + tx] = __float2half_rn(tile[tx][i]);
}

__global__ void k_bias2(const float* __restrict__ bs, const float* __restrict__ bd,
                        float* __restrict__ b2)
{
    int i = blockIdx.x * blockDim.x + threadIdx.x;
    if (i < HH) b2[i] = bs[i];
    else if (i < NH2) b2[i] = bd[i - HH];
}

__global__ void k_copy(float* d, const float* s, int n){ int i = blockIdx.x*blockDim.x + threadIdx.x; if (i < n) d[i] = s[i]; }

// ---------------- CSR build (per graph; deterministic) ----------------
__global__ void k_csr(const int* __restrict__ dst, int* __restrict__ offA,
                      int* __restrict__ degA, int* __restrict__ eix)
{
    __shared__ int cnt[NPG];
    __shared__ int basep[NPG];
    int g = blockIdx.x, tid = threadIdx.x;
    if (tid < NPG) cnt[tid] = 0;
    __syncthreads();
    if (tid < EPG) {
        int e = g * EPG + tid;
        atomicAdd(&cnt[dst[e] - g * NPG], 1);
    }
    __syncthreads();
    if (tid == 0) {
        int run = g * EPG;
        for (int i = 0; i < NPG; i++) {
            basep[i] = run;
            offA[g * NPG + i] = run;
            degA[g * NPG + i] = cnt[i];
            run += cnt[i];
        }
        for (int j = 0; j < EPG; j++) {
            int e = g * EPG + j;
            int dl = dst[e] - g * NPG;
            eix[basep[dl]++] = e;
        }
    }
}

// ---------------- edge kernels ----------------
// float4 loads: 8 halves / 8 floats per instruction
__global__ __launch_bounds__(256) void k_logits(const __half* __restrict__ f,
                                                const float* __restrict__ attn_a,
                                                const int* __restrict__ src,
                                                const int* __restrict__ dst,
                                                float* __restrict__ logits)
{
    int e = blockIdx.x;
    int h = threadIdx.x >> 5;
    int lane = threadIdx.x & 31;
    int s = src[e], d = dst[e];
    const float4* pf = (const float4*)(f + (size_t)s*NH2 + h*H);      // 8 halves per elt
    const float4* pd = (const float4*)(f + (size_t)d*NH2 + HH + h*H);
    const float4* pa = (const float4*)(attn_a + h*H);                 // 4 floats per elt
    float acc = 0.f;
    #pragma unroll
    for (int i = lane; i < H/8; i += 32) {
        float4 araw = pf[i];
        float4 braw = pd[i];
        float4 w0 = pa[2*i], w1 = pa[2*i + 1];
        const __half2* ah2 = (const __half2*)&araw;
        const __half2* bh2 = (const __half2*)&braw;
        const float* wf = &w0.x;   // w0,w1 contiguous on stack
        float wbuf[8] = { w0.x, w0.y, w0.z, w0.w, w1.x, w1.y, w1.z, w1.w };
        (void)wf;
        #pragma unroll
        for (int q = 0; q < 4; q++) {
            float2 a = __half22float2(ah2[q]);
            float2 b = __half22float2(bh2[q]);
            float v;
            v = a.x + b.x; v = v > 0.f ? v : 0.2f*v; acc += v * wbuf[2*q];
            v = a.y + b.y; v = v > 0.f ? v : 0.2f*v; acc += v * wbuf[2*q + 1];
        }
    }
    #pragma unroll
    for (int o = 16; o; o >>= 1) acc += __shfl_xor_sync(0xffffffffu, acc, o);
    if (lane == 0) logits[e*HEADS + h] = acc;
}

__global__ __launch_bounds__(256) void k_softmax(const float* __restrict__ logits,
                                                 const int* __restrict__ offA,
                                                 const int* __restrict__ degA,
                                                 const int* __restrict__ eix,
                                                 float* __restrict__ att)
{
    int n = blockIdx.x * 8 + (threadIdx.x >> 5);
    int lane = threadIdx.x & 31;
    int off = offA[n], deg = degA[n];
    int h = lane & 7, grp = lane >> 3;
    float m = -1e30f;
    for (int j = grp; j < deg; j += 4)
        m = fmaxf(m, logits[eix[off + j]*HEADS + h]);
    m = fmaxf(m, __shfl_xor_sync(0xffffffffu, m, 8));
    m = fmaxf(m, __shfl_xor_sync(0xffffffffu, m, 16));
    float s = 0.f;
    for (int j = grp; j < deg; j += 4)
        s += expf(logits[eix[off + j]*HEADS + h] - m);
    s += __shfl_xor_sync(0xffffffffu, s, 8);
    s += __shfl_xor_sync(0xffffffffu, s, 16);
    float inv = 1.f / s;
    for (int j = grp; j < deg; j += 4) {
        int ei = eix[off + j];
        att[ei*HEADS + h] = expf(logits[ei*HEADS + h] - m) * inv;
    }
}

// block per node; half2-vectorized; outputs fp16 ah + GRU input x (virtual nodes)
__global__ __launch_bounds__(256) void k_aggregate(const float* __restrict__ att,
                                                   const __half* __restrict__ f,
                                                   const int* __restrict__ src,
                                                   const int* __restrict__ offA,
                                                   const int* __restrict__ degA,
                                                   const int* __restrict__ eix,
                                                   __half* __restrict__ ah,
                                                   float* __restrict__ x)
{
    __shared__ float coef[96*HEADS];
    __shared__ int   srcs[96];
    int n = blockIdx.x, tid = threadIdx.x;
    int off = offA[n], deg = degA[n];
    int g = n / NPG, nl = n - g * NPG;
    for (int idx = tid; idx < deg*HEADS; idx += 256) {
        int j = idx >> 3, h = idx & 7;
        coef[idx] = att[eix[off + j]*HEADS + h] * 0.125f;
    }
    if (tid < deg) srcs[tid] = src[eix[off + tid]];
    __syncthreads();
    #pragma unroll
    for (int i2 = tid; i2 < H/2; i2 += 256) {      // half2 element pairs
        float vx = 0.f, vy = 0.f;
        for (int j = 0; j < deg; j++) {
            const __half2* p2 = (const __half2*)(f + (size_t)srcs[j]*NH2) + i2;
            const float* cj = coef + j*HEADS;
            #pragma unroll
            for (int h = 0; h < HEADS; h++) {
                float2 pv = __half22float2(p2[h*(H/2)]);
                vx += cj[h] * pv.x;
                vy += cj[h] * pv.y;
            }
        }
        size_t o2 = (size_t)n*(H/2) + i2;
        ((__half2*)ah)[o2] = __floats2half2_rn(vx, vy);
        if (nl == NPG - 1) ((float2*)x)[g*(H/2) + i2] = make_float2(vx, vy);
    }
}

__global__ void k_attn_out(const float* __restrict__ att, const int* __restrict__ eids,
                           float* __restrict__ out)
{
    int i = blockIdx.x*blockDim.x + threadIdx.x;
    if (i >= B*N_ATOM) return;
    int e = eids[i];
    float s = 0.f;
    #pragma unroll
    for (int h = 0; h < HEADS; h++) s += att[e*HEADS + h];
    out[i] = s * 0.125f;
}

// ---------------- batched NT SGEMM for GRU ----------------
#define BM 128
#define BN 128
#define BK 8
__global__ __launch_bounds__(256) void sgemm_nt2(
    const float* __restrict__ A0, const float* __restrict__ W0, const float* __restrict__ b0,
    float* __restrict__ C0,
    const float* __restrict__ A1, const float* __restrict__ W1, const float* __restrict__ b1,
    float* __restrict__ C1,
    int M, int N, int K)
{
    __shared__ float As[BK][BM];
    __shared__ float Bs[BK][BN];
    const float* A    = blockIdx.z ? A1 : A0;
    const float* W    = blockIdx.z ? W1 : W0;
    const float* bias = blockIdx.z ? b1 : b0;
    float*       C    = blockIdx.z ? C1 : C0;
    const int bx = blockIdx.x, by = blockIdx.y;
    const int tid = threadIdx.x;
    const int tx = tid & 15, ty = tid >> 4;
    const float* Ap = A + (size_t)by*BM*K;
    const float* Wp = W + (size_t)bx*BN*K;
    const int aRow = tid >> 1, aCol4 = (tid & 1) * 4;
    float acc[8][8];
    #pragma unroll
    for (int i = 0; i < 8; i++)
        #pragma unroll
        for (int j = 0; j < 8; j++) acc[i][j] = 0.f;
    for (int k0 = 0; k0 < K; k0 += BK) {
        float4 av = *(const float4*)(Ap + (size_t)aRow*K + k0 + aCol4);
        As[aCol4+0][aRow] = av.x; As[aCol4+1][aRow] = av.y;
        As[aCol4+2][aRow] = av.z; As[aCol4+3][aRow] = av.w;
        float4 wv = *(const float4*)(Wp + (size_t)aRow*K + k0 + aCol4);
        Bs[aCol4+0][aRow] = wv.x; Bs[aCol4+1][aRow] = wv.y;
        Bs[aCol4+2][aRow] = wv.z; Bs[aCol4+3][aRow] = wv.w;
        __syncthreads();
        #pragma unroll
        for (int k = 0; k < BK; k++) {
            float a[8], b[8];
            #pragma unroll
            for (int i = 0; i < 8; i++) a[i] = As[k][ty*8 + i];
            #pragma unroll
            for (int j = 0; j < 8; j++) b[j] = Bs[k][tx*8 + j];
            #pragma unroll
            for (int i = 0; i < 8; i++)
                #pragma unroll
                for (int j = 0; j < 8; j++)
                    acc[i][j] += a[i] * b[j];
        }
        __syncthreads();
    }
    #pragma unroll
    for (int i = 0; i < 8; i++) {
        int row = by*BM + ty*8 + i;
        #pragma unroll
        for (int j = 0; j < 8; j++) {
            int col = bx*BN + tx*8 + j;
            C[(size_t)row*N + col] = acc[i][j] + bias[col];
        }
    }
}

__global__ void k_gru(const float* __restrict__ gi, const float* __restrict__ gh,
                      float* __restrict__ mol, float* __restrict__ out_final)
{
    int i = blockIdx.x*blockDim.x + threadIdx.x;
    if (i >= B*H) return;
    int b = i / H, d = i - b*H;
    float ir = gi[b*G3H + d],       hr = gh[b*G3H + d];
    float iz = gi[b*G3H + H + d],   hz = gh[b*G3H + H + d];
    float in_= gi[b*G3H + 2*H + d], hn = gh[b*G3H + 2*H + d];
    float r = 1.f / (1.f + expf(-(ir + hr)));
    float z = 1.f / (1.f + expf(-(iz + hz)));
    float n = tanhf(in_ + r * hn);
    float hp = mol[i];
    float v = (1.f - z) * n + z * hp;
    v = v > 0.f ? v : 0.f;
    mol[i] = v;
    if (out_final) out_final[i] = v;
}

// ---------------- host ----------------
extern "C" void kernel_launch(void* const* d_in, const int* in_sizes, int n_in,
                              void* d_out, int out_size)
{
    const float* h_nodes  = (const float*)d_in[0];
    const float* mol_feat = (const float*)d_in[1];
    const float* W_src    = (const float*)d_in[2];
    const float* b_src    = (const float*)d_in[3];
    const float* W_dst    = (const float*)d_in[4];
    const float* b_dst    = (const float*)d_in[5];
    const float* attn_a   = (const float*)d_in[6];
    const float* W_ih     = (const float*)d_in[7];
    const float* W_hh     = (const float*)d_in[8];
    const float* b_ih     = (const float*)d_in[9];
    const float* b_hh     = (const float*)d_in[10];
    const int*   src      = (const int*)d_in[11];
    const int*   dst      = (const int*)d_in[12];
    const int*   vnids    = (const int*)d_in[13];  (void)vnids;
    const int*   eids     = (const int*)d_in[14];
    float* out = (float*)d_out;

    float *logits, *att, *mol, *x, *gi, *gh, *bias2;
    __half *f, *ah, *wh;
    int *offA, *degA, *eixp;
    cudaGetSymbolAddress((void**)&f,      g_f);
    cudaGetSymbolAddress((void**)&logits, g_logits);
    cudaGetSymbolAddress((void**)&att,    g_att);
    cudaGetSymbolAddress((void**)&mol,    g_mol);
    cudaGetSymbolAddress((void**)&x,      g_x);
    cudaGetSymbolAddress((void**)&gi,     g_gi);
    cudaGetSymbolAddress((void**)&gh,     g_gh);
    cudaGetSymbolAddress((void**)&bias2,  g_bias2);
    cudaGetSymbolAddress((void**)&ah,     g_ah);
    cudaGetSymbolAddress((void**)&wh,     g_wh);
    cudaGetSymbolAddress((void**)&offA,   g_offA);
    cudaGetSymbolAddress((void**)&degA,   g_degA);
    cudaGetSymbolAddress((void**)&eixp,   g_eix);

    cudaFuncSetAttribute(hmma_gemm, cudaFuncAttributeMaxDynamicSharedMemorySize, TC_SMEM);

    k_copy<<<(B*H + 255)/256, 256>>>(mol, mol_feat, B*H);
    k_csr<<<B, 160>>>(dst, offA, degA, eixp);
    k_halfA<<<(NN*H + 255)/256, 256>>>(h_nodes, ah, NN*H);

    for (int t = 0; t < T_STEPS; t++) {
        k_bias2<<<(NH2 + 255)/256, 256>>>(b_src + t*HH, b_dst + t*HH, bias2);
        k_halfWT2<<<dim3(2*HH/32, H/32), dim3(32, 8)>>>(
            W_src + (size_t)t*H*HH, W_dst + (size_t)t*H*HH, wh);

        dim3 gg(NH2/GN, NN/GM);   // 96 x 49
        hmma_gemm<<<gg, 256, TC_SMEM>>>(ah, wh, bias2, f);

        k_logits<<<EE, 256>>>(f, attn_a + (size_t)t*HEADS*H, src, dst, logits);
        k_softmax<<<NN/8, 256>>>(logits, offA, degA, eixp, att);
        k_aggregate<<<NN, 256>>>(att, f, src, offA, degA, eixp, ah, x);
        k_attn_out<<<(B*N_ATOM + 255)/256, 256>>>(att, eids, out + B*H + t*B*N_ATOM);

        sgemm_nt2<<<dim3(G3H/BN, B/BM, 2), 256>>>(
            x,   W_ih + (size_t)t*G3H*H, b_ih + t*G3H, gi,
            mol, W_hh + (size_t)t*G3H*H, b_hh + t*G3H, gh,
            B, G3H, H);
        k_gru<<<(B*H + 255)/256, 256>>>(gi, gh, mol, (t == T_STEPS-1) ? out : nullptr);
    }
}

// round 14
// speedup vs baseline: 1.1287x; 1.0204x over previous
#include <cuda_runtime.h>
#include <cuda_fp16.h>
#include <cstdint>

#define H 768
#define HEADS 8
#define T_STEPS 3
#define B 128
#define N_ATOM 48
#define NPG 49
#define EPG 144
#define NN (B*NPG)        // 6272 nodes
#define EE (B*EPG)        // 18432 edges
#define HH (HEADS*H)      // 6144
#define NH2 (2*HH)        // 12288 combined fs|fd columns
#define G3H (3*H)         // 2304

// ---------------- scratch (__device__ globals; no allocation) ----------------
__device__ __half   g_f[(size_t)NN*NH2];      // combined [fs | fd] per node, fp16
__device__ float    g_logits[EE*HEADS];
__device__ float    g_att[EE*HEADS];
__device__ float    g_mol[B*H];
__device__ float    g_x[B*H];
__device__ float    g_gi[B*G3H];
__device__ float    g_gh[B*G3H];
__device__ float    g_bias2[T_STEPS*NH2];
// fp16 buffers
__device__ __half g_ah[(size_t)NN*H];
__device__ __half g_wh[(size_t)T_STEPS*NH2*H];   // per-step transposed weights fp16
// CSR
__device__ int g_offA[NN];
__device__ int g_degA[NN];
__device__ int g_eix[EE];

// ---------------- PTX helpers ----------------
__device__ __forceinline__ uint32_t smem_u32(const void* p) {
    uint32_t a;
    asm("{ .reg .u64 t; cvta.to.shared.u64 t, %1; cvt.u32.u64 %0, t; }" : "=r"(a) : "l"(p));
    return a;
}
__device__ __forceinline__ void cp16(uint32_t saddr, const void* gptr) {
    asm volatile("cp.async.cg.shared.global [%0], [%1], 16;" :: "r"(saddr), "l"(gptr));
}
__device__ __forceinline__ void cp_commit() { asm volatile("cp.async.commit_group;"); }
__device__ __forceinline__ void cp_wait2() { asm volatile("cp.async.wait_group 2;"); }
__device__ __forceinline__ void cp_wait1() { asm volatile("cp.async.wait_group 1;"); }
__device__ __forceinline__ void cp_wait0() { asm volatile("cp.async.wait_group 0;"); }
__device__ __forceinline__ void ldm_x4(uint32_t* r, uint32_t addr) {
    asm volatile("ldmatrix.sync.aligned.m8n8.x4.shared.b16 {%0,%1,%2,%3}, [%4];"
                 : "=r"(r[0]), "=r"(r[1]), "=r"(r[2]), "=r"(r[3]) : "r"(addr));
}
__device__ __forceinline__ void mma_f16(float* c, const uint32_t* a, const uint32_t* b) {
    asm volatile(
        "mma.sync.aligned.m16n8k16.row.col.f32.f16.f16.f32 "
        "{%0,%1,%2,%3}, {%4,%5,%6,%7}, {%8,%9}, {%0,%1,%2,%3};"
        : "+f"(c[0]), "+f"(c[1]), "+f"(c[2]), "+f"(c[3])
        : "r"(a[0]), "r"(a[1]), "r"(a[2]), "r"(a[3]), "r"(b[0]), "r"(b[1]));
}

// ---------------- single-pass fp16 HMMA GEMM (R11 config + B ldm_x4) ----------------
#define GM 128
#define GN 128
#define GK 32
#define KCH (H/GK)       // 24
#define NSTG 4
#define ST_SZ 16384      // A 8K | B 8K
#define OFF_A 0
#define OFF_B 8192
#define TC_SMEM (NSTG*ST_SZ)   // 64KB

__global__ __launch_bounds__(256, 2) void hmma_gemm(
    const __half* __restrict__ Ah, const __half* __restrict__ Wh,
    const float* __restrict__ bias, __half* __restrict__ C)
{
    extern __shared__ char smem[];
    const uint32_t sb = smem_u32(smem);
    const int tid = threadIdx.x;
    const int wid = tid >> 5, lane = tid & 31;
    const int wm = wid >> 2, wn = wid & 3;
    const int m0 = blockIdx.y * GM, n0 = blockIdx.x * GN;

    const char* aP = (const char*)(Ah + (size_t)m0 * H);
    const char* bP = (const char*)(Wh + (size_t)n0 * H);

    float acc[4][4][4];
    #pragma unroll
    for (int i = 0; i < 4; i++)
        #pragma unroll
        for (int j = 0; j < 4; j++)
            #pragma unroll
            for (int q = 0; q < 4; q++) acc[i][j][q] = 0.f;

    auto load_stage = [&](int stage, int chunk) {
        uint32_t st = sb + stage * ST_SZ;
        int kb = chunk * 64;
        #pragma unroll
        for (int i = 0; i < 4; i++) {
            int buf = i >> 1;
            int rem = ((i & 1) << 8) + tid;
            int row = rem >> 2, ch = rem & 3;
            uint32_t off = (uint32_t)buf * 8192 + row * 64 + (((ch ^ ((row >> 1) & 3))) << 4);
            const char* base = (buf == 0) ? aP : bP;
            cp16(st + off, base + (size_t)row * (H*2) + kb + ch * 16);
        }
        cp_commit();
    };

    load_stage(0, 0);
    load_stage(1, 1);
    load_stage(2, 2);

    const int arow = lane & 15;
    const int akh  = lane >> 4;
    const int bgrp = lane >> 3;          // 0..3: (nt-parity, k-half)
    const int brow8 = lane & 7;

    for (int c = 0; c < KCH; c++) {
        if (c < KCH-2) cp_wait2(); else if (c == KCH-2) cp_wait1(); else cp_wait0();
        __syncthreads();
        if (c + 3 < KCH) load_stage((c + 3) % NSTG, c + 3);

        uint32_t st = sb + (c % NSTG) * ST_SZ;
        #pragma unroll
        for (int j = 0; j < 2; j++) {
            uint32_t ah[4][4];
            int ka = j * 2 + akh;
            #pragma unroll
            for (int mt = 0; mt < 4; mt++) {
                int row = wm * 64 + mt * 16 + arow;
                uint32_t off = row * 64 + ((ka ^ ((row >> 1) & 3)) << 4);
                ldm_x4(ah[mt], st + OFF_A + off);
            }
            #pragma unroll
            for (int ntp = 0; ntp < 4; ntp += 2) {
                uint32_t bq[4];   // bq[0..1]: nt=ntp, bq[2..3]: nt=ntp+1
                int row = wn * 32 + (ntp + (bgrp >> 1)) * 8 + brow8;
                int ch = j * 2 + (bgrp & 1);
                uint32_t off = row * 64 + ((ch ^ ((row >> 1) & 3)) << 4);
                ldm_x4(bq, st + OFF_B + off);
                #pragma unroll
                for (int mt = 0; mt < 4; mt++) {
                    mma_f16(acc[mt][ntp],     ah[mt], bq);
                    mma_f16(acc[mt][ntp + 1], ah[mt], bq + 2);
                }
            }
        }
    }

    const int g = lane >> 2, tq = lane & 3;
    #pragma unroll
    for (int mt = 0; mt < 4; mt++) {
        #pragma unroll
        for (int nt = 0; nt < 4; nt++) {
            int row = m0 + wm*64 + mt*16 + g;
            int col = n0 + wn*32 + nt*8 + tq*2;
            float b0 = bias[col], b1 = bias[col + 1];
            __half2 v0 = __floats2half2_rn(acc[mt][nt][0] + b0, acc[mt][nt][1] + b1);
            __half2 v1 = __floats2half2_rn(acc[mt][nt][2] + b0, acc[mt][nt][3] + b1);
            *(__half2*)&C[(size_t)row * NH2 + col] = v0;
            *(__half2*)&C[(size_t)(row + 8) * NH2 + col] = v1;
        }
    }
}

// ---------------- conversions ----------------
__global__ void k_halfA(const float* __restrict__ in, __half* __restrict__ o, int n)
{
    int i = blockIdx.x * blockDim.x + threadIdx.x;
    if (i < n) o[i] = __float2half_rn(in[i]);
}

__global__ void k_halfWT2(const float* __restrict__ Ws, const float* __restrict__ Wd,
                          __half* __restrict__ WT)
{
    __shared__ float tile[32][33];
    int bx = blockIdx.x;
    const int half_nb = HH/32;
    const float* W = (bx < half_nb) ? Ws : Wd;
    int rowoff = (bx < half_nb) ? 0 : HH;
    int n0 = ((bx < half_nb) ? bx : bx - half_nb) * 32;
    int k0 = blockIdx.y * 32;
    int tx = threadIdx.x, ty = threadIdx.y;
    #pragma unroll
    for (int i = ty; i < 32; i += 8)
        tile[i][tx] = W[(size_t)(k0 + i) * HH + n0 + tx];
    __syncthreads();
    #pragma unroll
    for (int i = ty; i < 32; i += 8)
        WT[(size_t)(rowoff + n0 + i) * H + k0 + tx] = __float2half_rn(tile[tx][i]);
}

__global__ void k_bias2(const float* __restrict__ bs, const float* __restrict__ bd,
                        float* __restrict__ b2)
{
    int i = blockIdx.x * blockDim.x + threadIdx.x;
    if (i < HH) b2[i] = bs[i];
    else if (i < NH2) b2[i] = bd[i - HH];
}

// ---------------- CSR build (per graph; deterministic) ----------------
__global__ void k_csr(const int* __restrict__ dst, int* __restrict__ offA,
                      int* __restrict__ degA, int* __restrict__ eix)
{
    __shared__ int cnt[NPG];
    __shared__ int basep[NPG];
    int g = blockIdx.x, tid = threadIdx.x;
    if (tid < NPG) cnt[tid] = 0;
    __syncthreads();
    if (tid < EPG) {
        int e = g * EPG + tid;
        atomicAdd(&cnt[dst[e] - g * NPG], 1);
    }
    __syncthreads();
    if (tid == 0) {
        int run = g * EPG;
        for (int i = 0; i < NPG; i++) {
            basep[i] = run;
            offA[g * NPG + i] = run;
            degA[g * NPG + i] = cnt[i];
            run += cnt[i];
        }
        for (int j = 0; j < EPG; j++) {
            int e = g * EPG + j;
            int dl = dst[e] - g * NPG;
            eix[basep[dl]++] = e;
        }
    }
}

// ---------------- edge kernels ----------------
__global__ __launch_bounds__(256) void k_logits(const __half* __restrict__ f,
                                                const float* __restrict__ attn_a,
                                                const int* __restrict__ src,
                                                const int* __restrict__ dst,
                                                float* __restrict__ logits)
{
    int e = blockIdx.x;
    int h = threadIdx.x >> 5;
    int lane = threadIdx.x & 31;
    int s = src[e], d = dst[e];
    const float4* pf = (const float4*)(f + (size_t)s*NH2 + h*H);
    const float4* pd = (const float4*)(f + (size_t)d*NH2 + HH + h*H);
    const float4* pa = (const float4*)(attn_a + h*H);
    float acc = 0.f;
    #pragma unroll
    for (int i = lane; i < H/8; i += 32) {
        float4 araw = pf[i];
        float4 braw = pd[i];
        float4 w0 = pa[2*i], w1 = pa[2*i + 1];
        const __half2* ah2 = (const __half2*)&araw;
        const __half2* bh2 = (const __half2*)&braw;
        float wbuf[8] = { w0.x, w0.y, w0.z, w0.w, w1.x, w1.y, w1.z, w1.w };
        #pragma unroll
        for (int q = 0; q < 4; q++) {
            float2 a = __half22float2(ah2[q]);
            float2 b = __half22float2(bh2[q]);
            float v;
            v = a.x + b.x; v = v > 0.f ? v : 0.2f*v; acc += v * wbuf[2*q];
            v = a.y + b.y; v = v > 0.f ? v : 0.2f*v; acc += v * wbuf[2*q + 1];
        }
    }
    #pragma unroll
    for (int o = 16; o; o >>= 1) acc += __shfl_xor_sync(0xffffffffu, acc, o);
    if (lane == 0) logits[e*HEADS + h] = acc;
}

__global__ __launch_bounds__(256) void k_softmax(const float* __restrict__ logits,
                                                 const int* __restrict__ offA,
                                                 const int* __restrict__ degA,
                                                 const int* __restrict__ eix,
                                                 float* __restrict__ att)
{
    int n = blockIdx.x * 8 + (threadIdx.x >> 5);
    int lane = threadIdx.x & 31;
    int off = offA[n], deg = degA[n];
    int h = lane & 7, grp = lane >> 3;
    float m = -1e30f;
    for (int j = grp; j < deg; j += 4)
        m = fmaxf(m, logits[eix[off + j]*HEADS + h]);
    m = fmaxf(m, __shfl_xor_sync(0xffffffffu, m, 8));
    m = fmaxf(m, __shfl_xor_sync(0xffffffffu, m, 16));
    float s = 0.f;
    for (int j = grp; j < deg; j += 4)
        s += expf(logits[eix[off + j]*HEADS + h] - m);
    s += __shfl_xor_sync(0xffffffffu, s, 8);
    s += __shfl_xor_sync(0xffffffffu, s, 16);
    float inv = 1.f / s;
    for (int j = grp; j < deg; j += 4) {
        int ei = eix[off + j];
        att[ei*HEADS + h] = expf(logits[ei*HEADS + h] - m) * inv;
    }
}

__global__ __launch_bounds__(256) void k_aggregate(const float* __restrict__ att,
                                                   const __half* __restrict__ f,
                                                   const int* __restrict__ src,
                                                   const int* __restrict__ offA,
                                                   const int* __restrict__ degA,
                                                   const int* __restrict__ eix,
                                                   __half* __restrict__ ah,
                                                   float* __restrict__ x)
{
    __shared__ float coef[96*HEADS];
    __shared__ int   srcs[96];
    int n = blockIdx.x, tid = threadIdx.x;
    int off = offA[n], deg = degA[n];
    int g = n / NPG, nl = n - g * NPG;
    for (int idx = tid; idx < deg*HEADS; idx += 256) {
        int j = idx >> 3, h = idx & 7;
        coef[idx] = att[eix[off + j]*HEADS + h] * 0.125f;
    }
    if (tid < deg) srcs[tid] = src[eix[off + tid]];
    __syncthreads();
    #pragma unroll
    for (int i2 = tid; i2 < H/2; i2 += 256) {
        float vx = 0.f, vy = 0.f;
        for (int j = 0; j < deg; j++) {
            const __half2* p2 = (const __half2*)(f + (size_t)srcs[j]*NH2) + i2;
            const float* cj = coef + j*HEADS;
            #pragma unroll
            for (int h = 0; h < HEADS; h++) {
                float2 pv = __half22float2(p2[h*(H/2)]);
                vx += cj[h] * pv.x;
                vy += cj[h] * pv.y;
            }
        }
        size_t o2 = (size_t)n*(H/2) + i2;
        ((__half2*)ah)[o2] = __floats2half2_rn(vx, vy);
        if (nl == NPG - 1) ((float2*)x)[g*(H/2) + i2] = make_float2(vx, vy);
    }
}

__global__ void k_attn_out(const float* __restrict__ att, const int* __restrict__ eids,
                           float* __restrict__ out)
{
    int i = blockIdx.x*blockDim.x + threadIdx.x;
    if (i >= B*N_ATOM) return;
    int e = eids[i];
    float s = 0.f;
    #pragma unroll
    for (int h = 0; h < HEADS; h++) s += att[e*HEADS + h];
    out[i] = s * 0.125f;
}

// ---------------- batched NT SGEMM for GRU ----------------
#define BM 128
#define BN 128
#define BK 8
__global__ __launch_bounds__(256) void sgemm_nt2(
    const float* __restrict__ A0, const float* __restrict__ W0, const float* __restrict__ b0,
    float* __restrict__ C0,
    const float* __restrict__ A1, const float* __restrict__ W1, const float* __restrict__ b1,
    float* __restrict__ C1,
    int M, int N, int K)
{
    __shared__ float As[BK][BM];
    __shared__ float Bs[BK][BN];
    const float* A    = blockIdx.z ? A1 : A0;
    const float* W    = blockIdx.z ? W1 : W0;
    const float* bias = blockIdx.z ? b1 : b0;
    float*       C    = blockIdx.z ? C1 : C0;
    const int bx = blockIdx.x, by = blockIdx.y;
    const int tid = threadIdx.x;
    const int tx = tid & 15, ty = tid >> 4;
    const float* Ap = A + (size_t)by*BM*K;
    const float* Wp = W + (size_t)bx*BN*K;
    const int aRow = tid >> 1, aCol4 = (tid & 1) * 4;
    float acc[8][8];
    #pragma unroll
    for (int i = 0; i < 8; i++)
        #pragma unroll
        for (int j = 0; j < 8; j++) acc[i][j] = 0.f;
    for (int k0 = 0; k0 < K; k0 += BK) {
        float4 av = *(const float4*)(Ap + (size_t)aRow*K + k0 + aCol4);
        As[aCol4+0][aRow] = av.x; As[aCol4+1][aRow] = av.y;
        As[aCol4+2][aRow] = av.z; As[aCol4+3][aRow] = av.w;
        float4 wv = *(const float4*)(Wp + (size_t)aRow*K + k0 + aCol4);
        Bs[aCol4+0][aRow] = wv.x; Bs[aCol4+1][aRow] = wv.y;
        Bs[aCol4+2][aRow] = wv.z; Bs[aCol4+3][aRow] = wv.w;
        __syncthreads();
        #pragma unroll
        for (int k = 0; k < BK; k++) {
            float a[8], b[8];
            #pragma unroll
            for (int i = 0; i < 8; i++) a[i] = As[k][ty*8 + i];
            #pragma unroll
            for (int j = 0; j < 8; j++) b[j] = Bs[k][tx*8 + j];
            #pragma unroll
            for (int i = 0; i < 8; i++)
                #pragma unroll
                for (int j = 0; j < 8; j++)
                    acc[i][j] += a[i] * b[j];
        }
        __syncthreads();
    }
    #pragma unroll
    for (int i = 0; i < 8; i++) {
        int row = by*BM + ty*8 + i;
        #pragma unroll
        for (int j = 0; j < 8; j++) {
            int col = bx*BN + tx*8 + j;
            C[(size_t)row*N + col] = acc[i][j] + bias[col];
        }
    }
}

__global__ void k_gru(const float* __restrict__ gi, const float* __restrict__ gh,
                      const float* __restrict__ hprev, float* __restrict__ mol,
                      float* __restrict__ out_final)
{
    int i = blockIdx.x*blockDim.x + threadIdx.x;
    if (i >= B*H) return;
    int b = i / H, d = i - b*H;
    float ir = gi[b*G3H + d],       hr = gh[b*G3H + d];
    float iz = gi[b*G3H + H + d],   hz = gh[b*G3H + H + d];
    float in_= gi[b*G3H + 2*H + d], hn = gh[b*G3H + 2*H + d];
    float r = 1.f / (1.f + expf(-(ir + hr)));
    float z = 1.f / (1.f + expf(-(iz + hz)));
    float n = tanhf(in_ + r * hn);
    float hp = hprev[i];
    float v = (1.f - z) * n + z * hp;
    v = v > 0.f ? v : 0.f;
    mol[i] = v;
    if (out_final) out_final[i] = v;
}

// ---------------- host ----------------
extern "C" void kernel_launch(void* const* d_in, const int* in_sizes, int n_in,
                              void* d_out, int out_size)
{
    const float* h_nodes  = (const float*)d_in[0];
    const float* mol_feat = (const float*)d_in[1];
    const float* W_src    = (const float*)d_in[2];
    const float* b_src    = (const float*)d_in[3];
    const float* W_dst    = (const float*)d_in[4];
    const float* b_dst    = (const float*)d_in[5];
    const float* attn_a   = (const float*)d_in[6];
    const float* W_ih     = (const float*)d_in[7];
    const float* W_hh     = (const float*)d_in[8];
    const float* b_ih     = (const float*)d_in[9];
    const float* b_hh     = (const float*)d_in[10];
    const int*   src      = (const int*)d_in[11];
    const int*   dst      = (const int*)d_in[12];
    const int*   vnids    = (const int*)d_in[13];  (void)vnids;
    const int*   eids     = (const int*)d_in[14];
    float* out = (float*)d_out;

    float *logits, *att, *mol, *x, *gi, *gh, *bias2;
    __half *f, *ah, *wh;
    int *offA, *degA, *eixp;
    cudaGetSymbolAddress((void**)&f,      g_f);
    cudaGetSymbolAddress((void**)&logits, g_logits);
    cudaGetSymbolAddress((void**)&att,    g_att);
    cudaGetSymbolAddress((void**)&mol,    g_mol);
    cudaGetSymbolAddress((void**)&x,      g_x);
    cudaGetSymbolAddress((void**)&gi,     g_gi);
    cudaGetSymbolAddress((void**)&gh,     g_gh);
    cudaGetSymbolAddress((void**)&bias2,  g_bias2);
    cudaGetSymbolAddress((void**)&ah,     g_ah);
    cudaGetSymbolAddress((void**)&wh,     g_wh);
    cudaGetSymbolAddress((void**)&offA,   g_offA);
    cudaGetSymbolAddress((void**)&degA,   g_degA);
    cudaGetSymbolAddress((void**)&eixp,   g_eix);

    cudaFuncSetAttribute(hmma_gemm, cudaFuncAttributeMaxDynamicSharedMemorySize, TC_SMEM);

    // one-time host-side stream/event setup (no device work, no device memory)
    static cudaStream_t s2 = nullptr;
    static cudaEvent_t evFork, evW[T_STEPS];
    if (!s2) {
        cudaStreamCreateWithFlags(&s2, cudaStreamNonBlocking);
        cudaEventCreateWithFlags(&evFork, cudaEventDisableTiming);
        for (int t = 0; t < T_STEPS; t++)
            cudaEventCreateWithFlags(&evW[t], cudaEventDisableTiming);
    }

    // fork: weight conversions for ALL steps run on s2, overlapping the main chain
    cudaEventRecord(evFork, 0);
    cudaStreamWaitEvent(s2, evFork, 0);
    for (int t = 0; t < T_STEPS; t++) {
        k_bias2<<<(NH2 + 255)/256, 256, 0, s2>>>(b_src + t*HH, b_dst + t*HH,
                                                 bias2 + t*NH2);
        k_halfWT2<<<dim3(2*HH/32, H/32), dim3(32, 8), 0, s2>>>(
            W_src + (size_t)t*H*HH, W_dst + (size_t)t*H*HH, wh + (size_t)t*NH2*H);
        cudaEventRecord(evW[t], s2);
    }

    k_csr<<<B, 160>>>(dst, offA, degA, eixp);
    k_halfA<<<(NN*H + 255)/256, 256>>>(h_nodes, ah, NN*H);

    for (int t = 0; t < T_STEPS; t++) {
        cudaStreamWaitEvent(0, evW[t], 0);   // join conversion for this step

        dim3 gg(NH2/GN, NN/GM);   // 96 x 49
        hmma_gemm<<<gg, 256, TC_SMEM>>>(ah, wh + (size_t)t*NH2*H, bias2 + t*NH2, f);

        k_logits<<<EE, 256>>>(f, attn_a + (size_t)t*HEADS*H, src, dst, logits);
        k_softmax<<<NN/8, 256>>>(logits, offA, degA, eixp, att);
        k_aggregate<<<NN, 256>>>(att, f, src, offA, degA, eixp, ah, x);
        k_attn_out<<<(B*N_ATOM + 255)/256, 256>>>(att, eids, out + B*H + t*B*N_ATOM);

        const float* hprev = (t == 0) ? mol_feat : mol;
        sgemm_nt2<<<dim3(G3H/BN, B/BM, 2), 256>>>(
            x,     W_ih + (size_t)t*G3H*H, b_ih + t*G3H, gi,
            hprev, W_hh + (size_t)t*G3H*H, b_hh + t*G3H, gh,
            B, G3H, H);
        k_gru<<<(B*H + 255)/256, 256>>>(gi, gh, hprev, mol,
                                        (t == T_STEPS-1) ? out : nullptr);
    }
}

// round 15
// speedup vs baseline: 1.3218x; 1.1711x over previous
#include <cuda_runtime.h>
#include <cuda_fp16.h>
#include <cstdint>

#define H 768
#define HEADS 8
#define T_STEPS 3
#define B 128
#define N_ATOM 48
#define NPG 49
#define EPG 144
#define NN (B*NPG)        // 6272 nodes
#define EE (B*EPG)        // 18432 edges
#define HH (HEADS*H)      // 6144
#define NH2 (2*HH)        // 12288 combined fs|fd columns
#define G3H (3*H)         // 2304

// ---------------- scratch (__device__ globals; no allocation) ----------------
__device__ __half   g_f[(size_t)NN*NH2];
__device__ float    g_logits[EE*HEADS];
__device__ float    g_att[EE*HEADS];
__device__ float    g_mol[B*H];
__device__ float    g_x[B*H];
__device__ float    g_gi[B*G3H];
__device__ float    g_gh[B*G3H];
__device__ float    g_bias2[T_STEPS*NH2];
__device__ __half   g_ah[(size_t)NN*H];
__device__ __half   g_wh[(size_t)T_STEPS*NH2*H];
__device__ int g_offA[NN];
__device__ int g_degA[NN];
__device__ int g_eix[EE];

// ---------------- PTX helpers ----------------
__device__ __forceinline__ uint32_t smem_u32(const void* p) {
    uint32_t a;
    asm("{ .reg .u64 t; cvta.to.shared.u64 t, %1; cvt.u32.u64 %0, t; }" : "=r"(a) : "l"(p));
    return a;
}
__device__ __forceinline__ void cp16(uint32_t saddr, const void* gptr) {
    asm volatile("cp.async.cg.shared.global [%0], [%1], 16;" :: "r"(saddr), "l"(gptr));
}
__device__ __forceinline__ void cp_commit() { asm volatile("cp.async.commit_group;"); }
__device__ __forceinline__ void cp_wait2() { asm volatile("cp.async.wait_group 2;"); }
__device__ __forceinline__ void cp_wait1() { asm volatile("cp.async.wait_group 1;"); }
__device__ __forceinline__ void cp_wait0() { asm volatile("cp.async.wait_group 0;"); }
__device__ __forceinline__ void ldm_x4(uint32_t* r, uint32_t addr) {
    asm volatile("ldmatrix.sync.aligned.m8n8.x4.shared.b16 {%0,%1,%2,%3}, [%4];"
                 : "=r"(r[0]), "=r"(r[1]), "=r"(r[2]), "=r"(r[3]) : "r"(addr));
}
__device__ __forceinline__ void mma_f16(float* c, const uint32_t* a, const uint32_t* b) {
    asm volatile(
        "mma.sync.aligned.m16n8k16.row.col.f32.f16.f16.f32 "
        "{%0,%1,%2,%3}, {%4,%5,%6,%7}, {%8,%9}, {%0,%1,%2,%3};"
        : "+f"(c[0]), "+f"(c[1]), "+f"(c[2]), "+f"(c[3])
        : "r"(a[0]), "r"(a[1]), "r"(a[2]), "r"(a[3]), "r"(b[0]), "r"(b[1]));
}

// ---------------- single-pass fp16 HMMA GEMM (R14 config) ----------------
#define GM 128
#define GN 128
#define GK 32
#define KCH (H/GK)       // 24
#define NSTG 4
#define ST_SZ 16384
#define OFF_A 0
#define OFF_B 8192
#define TC_SMEM (NSTG*ST_SZ)   // 64KB

__global__ __launch_bounds__(256, 2) void hmma_gemm(
    const __half* __restrict__ Ah, const __half* __restrict__ Wh,
    const float* __restrict__ bias, __half* __restrict__ C)
{
    extern __shared__ char smem[];
    const uint32_t sb = smem_u32(smem);
    const int tid = threadIdx.x;
    const int wid = tid >> 5, lane = tid & 31;
    const int wm = wid >> 2, wn = wid & 3;
    const int m0 = blockIdx.y * GM, n0 = blockIdx.x * GN;

    const char* aP = (const char*)(Ah + (size_t)m0 * H);
    const char* bP = (const char*)(Wh + (size_t)n0 * H);

    float acc[4][4][4];
    #pragma unroll
    for (int i = 0; i < 4; i++)
        #pragma unroll
        for (int j = 0; j < 4; j++)
            #pragma unroll
            for (int q = 0; q < 4; q++) acc[i][j][q] = 0.f;

    auto load_stage = [&](int stage, int chunk) {
        uint32_t st = sb + stage * ST_SZ;
        int kb = chunk * 64;
        #pragma unroll
        for (int i = 0; i < 4; i++) {
            int buf = i >> 1;
            int rem = ((i & 1) << 8) + tid;
            int row = rem >> 2, ch = rem & 3;
            uint32_t off = (uint32_t)buf * 8192 + row * 64 + (((ch ^ ((row >> 1) & 3))) << 4);
            const char* base = (buf == 0) ? aP : bP;
            cp16(st + off, base + (size_t)row * (H*2) + kb + ch * 16);
        }
        cp_commit();
    };

    load_stage(0, 0);
    load_stage(1, 1);
    load_stage(2, 2);

    const int arow = lane & 15;
    const int akh  = lane >> 4;
    const int bgrp = lane >> 3;
    const int brow8 = lane & 7;

    for (int c = 0; c < KCH; c++) {
        if (c < KCH-2) cp_wait2(); else if (c == KCH-2) cp_wait1(); else cp_wait0();
        __syncthreads();
        if (c + 3 < KCH) load_stage((c + 3) % NSTG, c + 3);

        uint32_t st = sb + (c % NSTG) * ST_SZ;
        #pragma unroll
        for (int j = 0; j < 2; j++) {
            uint32_t ah[4][4];
            int ka = j * 2 + akh;
            #pragma unroll
            for (int mt = 0; mt < 4; mt++) {
                int row = wm * 64 + mt * 16 + arow;
                uint32_t off = row * 64 + ((ka ^ ((row >> 1) & 3)) << 4);
                ldm_x4(ah[mt], st + OFF_A + off);
            }
            #pragma unroll
            for (int ntp = 0; ntp < 4; ntp += 2) {
                uint32_t bq[4];
                int row = wn * 32 + (ntp + (bgrp >> 1)) * 8 + brow8;
                int ch = j * 2 + (bgrp & 1);
                uint32_t off = row * 64 + ((ch ^ ((row >> 1) & 3)) << 4);
                ldm_x4(bq, st + OFF_B + off);
                #pragma unroll
                for (int mt = 0; mt < 4; mt++) {
                    mma_f16(acc[mt][ntp],     ah[mt], bq);
                    mma_f16(acc[mt][ntp + 1], ah[mt], bq + 2);
                }
            }
        }
    }

    const int g = lane >> 2, tq = lane & 3;
    #pragma unroll
    for (int mt = 0; mt < 4; mt++) {
        #pragma unroll
        for (int nt = 0; nt < 4; nt++) {
            int row = m0 + wm*64 + mt*16 + g;
            int col = n0 + wn*32 + nt*8 + tq*2;
            float b0 = bias[col], b1 = bias[col + 1];
            __half2 v0 = __floats2half2_rn(acc[mt][nt][0] + b0, acc[mt][nt][1] + b1);
            __half2 v1 = __floats2half2_rn(acc[mt][nt][2] + b0, acc[mt][nt][3] + b1);
            *(__half2*)&C[(size_t)row * NH2 + col] = v0;
            *(__half2*)&C[(size_t)(row + 8) * NH2 + col] = v1;
        }
    }
}

// ---------------- conversions ----------------
__global__ void k_halfA(const float* __restrict__ in, __half* __restrict__ o, int n)
{
    int i = blockIdx.x * blockDim.x + threadIdx.x;
    if (i < n) o[i] = __float2half_rn(in[i]);
}

// weights + bias in one launch
__global__ void k_halfWT2(const float* __restrict__ Ws, const float* __restrict__ Wd,
                          const float* __restrict__ bs, const float* __restrict__ bd,
                          __half* __restrict__ WT, float* __restrict__ b2)
{
    __shared__ float tile[32][33];
    int bx = blockIdx.x;
    const int half_nb = HH/32;
    const bool isSrc = (bx < half_nb);
    const float* W = isSrc ? Ws : Wd;
    int rowoff = isSrc ? 0 : HH;
    int n0 = (isSrc ? bx : bx - half_nb) * 32;
    int k0 = blockIdx.y * 32;
    int tx = threadIdx.x, ty = threadIdx.y;
    if (blockIdx.y == 0 && ty == 0)
        b2[rowoff + n0 + tx] = isSrc ? bs[n0 + tx] : bd[n0 + tx];
    #pragma unroll
    for (int i = ty; i < 32; i += 8)
        tile[i][tx] = W[(size_t)(k0 + i) * HH + n0 + tx];
    __syncthreads();
    #pragma unroll
    for (int i = ty; i < 32; i += 8)
        WT[(size_t)(rowoff + n0 + i) * H + k0 + tx] = __float2half_rn(tile[tx][i]);
}

// ---------------- CSR build ----------------
__global__ void k_csr(const int* __restrict__ dst, int* __restrict__ offA,
                      int* __restrict__ degA, int* __restrict__ eix)
{
    __shared__ int cnt[NPG];
    __shared__ int basep[NPG];
    int g = blockIdx.x, tid = threadIdx.x;
    if (tid < NPG) cnt[tid] = 0;
    __syncthreads();
    if (tid < EPG) {
        int e = g * EPG + tid;
        atomicAdd(&cnt[dst[e] - g * NPG], 1);
    }
    __syncthreads();
    if (tid == 0) {
        int run = g * EPG;
        for (int i = 0; i < NPG; i++) {
            basep[i] = run;
            offA[g * NPG + i] = run;
            degA[g * NPG + i] = cnt[i];
            run += cnt[i];
        }
        for (int j = 0; j < EPG; j++) {
            int e = g * EPG + j;
            int dl = dst[e] - g * NPG;
            eix[basep[dl]++] = e;
        }
    }
}

// ---------------- edge kernels ----------------
#define LOG_GRID 4736
__global__ __launch_bounds__(256) void k_logits(const __half* __restrict__ f,
                                                const float* __restrict__ attn_a,
                                                const int* __restrict__ src,
                                                const int* __restrict__ dst,
                                                float* __restrict__ logits)
{
    int h = threadIdx.x >> 5;
    int lane = threadIdx.x & 31;
    const float4* pa = (const float4*)(attn_a + h*H);
    for (int e = blockIdx.x; e < EE; e += LOG_GRID) {
        int s = src[e], d = dst[e];
        const float4* pf = (const float4*)(f + (size_t)s*NH2 + h*H);
        const float4* pd = (const float4*)(f + (size_t)d*NH2 + HH + h*H);
        float acc = 0.f;
        #pragma unroll
        for (int i = lane; i < H/8; i += 32) {
            float4 araw = pf[i];
            float4 braw = pd[i];
            float4 w0 = pa[2*i], w1 = pa[2*i + 1];
            const __half2* ah2 = (const __half2*)&araw;
            const __half2* bh2 = (const __half2*)&braw;
            float wbuf[8] = { w0.x, w0.y, w0.z, w0.w, w1.x, w1.y, w1.z, w1.w };
            #pragma unroll
            for (int q = 0; q < 4; q++) {
                float2 a = __half22float2(ah2[q]);
                float2 b = __half22float2(bh2[q]);
                float v;
                v = a.x + b.x; v = v > 0.f ? v : 0.2f*v; acc += v * wbuf[2*q];
                v = a.y + b.y; v = v > 0.f ? v : 0.2f*v; acc += v * wbuf[2*q + 1];
            }
        }
        #pragma unroll
        for (int o = 16; o; o >>= 1) acc += __shfl_xor_sync(0xffffffffu, acc, o);
        if (lane == 0) logits[e*HEADS + h] = acc;
    }
}

// softmax per node + fused virtual-edge attention output
__global__ __launch_bounds__(256) void k_softmax(const float* __restrict__ logits,
                                                 const int* __restrict__ offA,
                                                 const int* __restrict__ degA,
                                                 const int* __restrict__ eix,
                                                 float* __restrict__ att,
                                                 float* __restrict__ attn_out)
{
    int n = blockIdx.x * 8 + (threadIdx.x >> 5);
    int lane = threadIdx.x & 31;
    int off = offA[n], deg = degA[n];
    int h = lane & 7, grp = lane >> 3;
    int g = n / NPG, nl = n - g * NPG;
    float m = -1e30f;
    for (int j = grp; j < deg; j += 4)
        m = fmaxf(m, logits[eix[off + j]*HEADS + h]);
    m = fmaxf(m, __shfl_xor_sync(0xffffffffu, m, 8));
    m = fmaxf(m, __shfl_xor_sync(0xffffffffu, m, 16));
    float s = 0.f;
    for (int j = grp; j < deg; j += 4)
        s += expf(logits[eix[off + j]*HEADS + h] - m);
    s += __shfl_xor_sync(0xffffffffu, s, 8);
    s += __shfl_xor_sync(0xffffffffu, s, 16);
    float inv = 1.f / s;
    bool isVirt = (nl == NPG - 1);
    for (int j = grp; j < deg; j += 4) {
        int ei = eix[off + j];
        float a = expf(logits[ei*HEADS + h] - m) * inv;
        att[ei*HEADS + h] = a;
        if (isVirt) {
            // head-mean within this octet (lanes grp*8 .. grp*8+7 hold h=0..7)
            float sm = a;
            sm += __shfl_xor_sync(0xffffffffu, sm, 1);
            sm += __shfl_xor_sync(0xffffffffu, sm, 2);
            sm += __shfl_xor_sync(0xffffffffu, sm, 4);
            if (h == 0) attn_out[g*N_ATOM + j] = sm * 0.125f;
        }
    }
}

__global__ __launch_bounds__(256) void k_aggregate(const float* __restrict__ att,
                                                   const __half* __restrict__ f,
                                                   const int* __restrict__ src,
                                                   const int* __restrict__ offA,
                                                   const int* __restrict__ degA,
                                                   const int* __restrict__ eix,
                                                   __half* __restrict__ ah,
                                                   float* __restrict__ x)
{
    __shared__ float coef[96*HEADS];
    __shared__ int   srcs[96];
    int n = blockIdx.x, tid = threadIdx.x;
    int off = offA[n], deg = degA[n];
    int g = n / NPG, nl = n - g * NPG;
    for (int idx = tid; idx < deg*HEADS; idx += 256) {
        int j = idx >> 3, h = idx & 7;
        coef[idx] = att[eix[off + j]*HEADS + h] * 0.125f;
    }
    if (tid < deg) srcs[tid] = src[eix[off + tid]];
    __syncthreads();
    #pragma unroll
    for (int i2 = tid; i2 < H/2; i2 += 256) {
        float vx = 0.f, vy = 0.f;
        for (int j = 0; j < deg; j++) {
            const __half2* p2 = (const __half2*)(f + (size_t)srcs[j]*NH2) + i2;
            const float* cj = coef + j*HEADS;
            #pragma unroll
            for (int h = 0; h < HEADS; h++) {
                float2 pv = __half22float2(p2[h*(H/2)]);
                vx += cj[h] * pv.x;
                vy += cj[h] * pv.y;
            }
        }
        size_t o2 = (size_t)n*(H/2) + i2;
        ((__half2*)ah)[o2] = __floats2half2_rn(vx, vy);
        if (nl == NPG - 1) ((float2*)x)[g*(H/2) + i2] = make_float2(vx, vy);
    }
}

// ---------------- batched NT SGEMM for GRU: 64x64 tiles, 144 blocks ----------------
#define BM2 64
#define BN2 64
#define BK2 16
__global__ __launch_bounds__(256) void sgemm_nt2(
    const float* __restrict__ A0, const float* __restrict__ W0, const float* __restrict__ b0,
    float* __restrict__ C0,
    const float* __restrict__ A1, const float* __restrict__ W1, const float* __restrict__ b1,
    float* __restrict__ C1,
    int M, int N, int K)
{
    __shared__ float As[BK2][BM2+1];
    __shared__ float Bs[BK2][BN2+1];
    const float* A    = blockIdx.z ? A1 : A0;
    const float* W    = blockIdx.z ? W1 : W0;
    const float* bias = blockIdx.z ? b1 : b0;
    float*       C    = blockIdx.z ? C1 : C0;
    const int bx = blockIdx.x, by = blockIdx.y;
    const int tid = threadIdx.x;
    const int tx = tid & 15, ty = tid >> 4;
    const float* Ap = A + (size_t)by*BM2*K;
    const float* Wp = W + (size_t)bx*BN2*K;
    const int lr = tid >> 2;          // 0..63
    const int lc = (tid & 3) * 4;     // 0,4,8,12
    float acc[4][4];
    #pragma unroll
    for (int i = 0; i < 4; i++)
        #pragma unroll
        for (int j = 0; j < 4; j++) acc[i][j] = 0.f;
    for (int k0 = 0; k0 < K; k0 += BK2) {
        float4 av = *(const float4*)(Ap + (size_t)lr*K + k0 + lc);
        As[lc+0][lr] = av.x; As[lc+1][lr] = av.y;
        As[lc+2][lr] = av.z; As[lc+3][lr] = av.w;
        float4 wv = *(const float4*)(Wp + (size_t)lr*K + k0 + lc);
        Bs[lc+0][lr] = wv.x; Bs[lc+1][lr] = wv.y;
        Bs[lc+2][lr] = wv.z; Bs[lc+3][lr] = wv.w;
        __syncthreads();
        #pragma unroll
        for (int k = 0; k < BK2; k++) {
            float a[4], b[4];
            #pragma unroll
            for (int i = 0; i < 4; i++) a[i] = As[k][ty*4 + i];
            #pragma unroll
            for (int j = 0; j < 4; j++) b[j] = Bs[k][tx*4 + j];
            #pragma unroll
            for (int i = 0; i < 4; i++)
                #pragma unroll
                for (int j = 0; j < 4; j++)
                    acc[i][j] += a[i] * b[j];
        }
        __syncthreads();
    }
    #pragma unroll
    for (int i = 0; i < 4; i++) {
        int row = by*BM2 + ty*4 + i;
        #pragma unroll
        for (int j = 0; j < 4; j++) {
            int col = bx*BN2 + tx*4 + j;
            C[(size_t)row*N + col] = acc[i][j] + bias[col];
        }
    }
}

__global__ void k_gru(const float* __restrict__ gi, const float* __restrict__ gh,
                      const float* __restrict__ hprev, float* __restrict__ mol,
                      float* __restrict__ out_final)
{
    int i = blockIdx.x*blockDim.x + threadIdx.x;
    if (i >= B*H) return;
    int b = i / H, d = i - b*H;
    float ir = gi[b*G3H + d],       hr = gh[b*G3H + d];
    float iz = gi[b*G3H + H + d],   hz = gh[b*G3H + H + d];
    float in_= gi[b*G3H + 2*H + d], hn = gh[b*G3H + 2*H + d];
    float r = 1.f / (1.f + expf(-(ir + hr)));
    float z = 1.f / (1.f + expf(-(iz + hz)));
    float n = tanhf(in_ + r * hn);
    float hp = hprev[i];
    float v = (1.f - z) * n + z * hp;
    v = v > 0.f ? v : 0.f;
    mol[i] = v;
    if (out_final) out_final[i] = v;
}

// ---------------- host ----------------
extern "C" void kernel_launch(void* const* d_in, const int* in_sizes, int n_in,
                              void* d_out, int out_size)
{
    const float* h_nodes  = (const float*)d_in[0];
    const float* mol_feat = (const float*)d_in[1];
    const float* W_src    = (const float*)d_in[2];
    const float* b_src    = (const float*)d_in[3];
    const float* W_dst    = (const float*)d_in[4];
    const float* b_dst    = (const float*)d_in[5];
    const float* attn_a   = (const float*)d_in[6];
    const float* W_ih     = (const float*)d_in[7];
    const float* W_hh     = (const float*)d_in[8];
    const float* b_ih     = (const float*)d_in[9];
    const float* b_hh     = (const float*)d_in[10];
    const int*   src      = (const int*)d_in[11];
    const int*   dst      = (const int*)d_in[12];
    const int*   vnids    = (const int*)d_in[13];  (void)vnids;
    const int*   eids     = (const int*)d_in[14];  (void)eids;
    float* out = (float*)d_out;

    float *logits, *att, *mol, *x, *gi, *gh, *bias2;
    __half *f, *ah, *wh;
    int *offA, *degA, *eixp;
    cudaGetSymbolAddress((void**)&f,      g_f);
    cudaGetSymbolAddress((void**)&logits, g_logits);
    cudaGetSymbolAddress((void**)&att,    g_att);
    cudaGetSymbolAddress((void**)&mol,    g_mol);
    cudaGetSymbolAddress((void**)&x,      g_x);
    cudaGetSymbolAddress((void**)&gi,     g_gi);
    cudaGetSymbolAddress((void**)&gh,     g_gh);
    cudaGetSymbolAddress((void**)&bias2,  g_bias2);
    cudaGetSymbolAddress((void**)&ah,     g_ah);
    cudaGetSymbolAddress((void**)&wh,     g_wh);
    cudaGetSymbolAddress((void**)&offA,   g_offA);
    cudaGetSymbolAddress((void**)&degA,   g_degA);
    cudaGetSymbolAddress((void**)&eixp,   g_eix);

    cudaFuncSetAttribute(hmma_gemm, cudaFuncAttributeMaxDynamicSharedMemorySize, TC_SMEM);

    static cudaStream_t s2 = nullptr;
    static cudaEvent_t evFork, evW[T_STEPS];
    if (!s2) {
        cudaStreamCreateWithFlags(&s2, cudaStreamNonBlocking);
        cudaEventCreateWithFlags(&evFork, cudaEventDisableTiming);
        for (int t = 0; t < T_STEPS; t++)
            cudaEventCreateWithFlags(&evW[t], cudaEventDisableTiming);
    }

    // fork: weight+bias conversions for ALL steps on s2
    cudaEventRecord(evFork, 0);
    cudaStreamWaitEvent(s2, evFork, 0);
    for (int t = 0; t < T_STEPS; t++) {
        k_halfWT2<<<dim3(2*HH/32, H/32), dim3(32, 8), 0, s2>>>(
            W_src + (size_t)t*H*HH, W_dst + (size_t)t*H*HH,
            b_src + t*HH, b_dst + t*HH,
            wh + (size_t)t*NH2*H, bias2 + t*NH2);
        cudaEventRecord(evW[t], s2);
    }

    k_csr<<<B, 160>>>(dst, offA, degA, eixp);
    k_halfA<<<(NN*H + 255)/256, 256>>>(h_nodes, ah, NN*H);

    for (int t = 0; t < T_STEPS; t++) {
        cudaStreamWaitEvent(0, evW[t], 0);

        dim3 gg(NH2/GN, NN/GM);   // 96 x 49
        hmma_gemm<<<gg, 256, TC_SMEM>>>(ah, wh + (size_t)t*NH2*H, bias2 + t*NH2, f);

        k_logits<<<LOG_GRID, 256>>>(f, attn_a + (size_t)t*HEADS*H, src, dst, logits);
        k_softmax<<<NN/8, 256>>>(logits, offA, degA, eixp, att,
                                 out + B*H + t*B*N_ATOM);
        k_aggregate<<<NN, 256>>>(att, f, src, offA, degA, eixp, ah, x);

        const float* hprev = (t == 0) ? mol_feat : mol;
        sgemm_nt2<<<dim3(G3H/BN2, B/BM2, 2), 256>>>(
            x,     W_ih + (size_t)t*G3H*H, b_ih + t*G3H, gi,
            hprev, W_hh + (size_t)t*G3H*H, b_hh + t*G3H, gh,
            B, G3H, H);
        k_gru<<<(B*H + 255)/256, 256>>>(gi, gh, hprev, mol,
                                        (t == T_STEPS-1) ? out : nullptr);
    }
}

// round 16
// speedup vs baseline: 1.3673x; 1.0345x over previous
#include <cuda_runtime.h>
#include <cuda_fp16.h>
#include <cstdint>

#define H 768
#define HEADS 8
#define T_STEPS 3
#define B 128
#define N_ATOM 48
#define NPG 49
#define EPG 144
#define NN (B*NPG)        // 6272 nodes
#define EE (B*EPG)        // 18432 edges
#define HH (HEADS*H)      // 6144
#define NH2 (2*HH)        // 12288 combined fs|fd columns
#define G3H (3*H)         // 2304

// ---------------- scratch (__device__ globals; no allocation) ----------------
__device__ __half   g_f[(size_t)NN*NH2];
__device__ float    g_logits[EE*HEADS];
__device__ float    g_mol[B*H];
__device__ float    g_x[2][B*H];          // double-buffered (t parity)
__device__ float    g_gi[B*G3H];
__device__ float    g_gh[B*G3H];
__device__ float    g_bias2[T_STEPS*NH2];
__device__ __half   g_ah[(size_t)NN*H];
__device__ __half   g_wh[(size_t)T_STEPS*NH2*H];
__device__ int g_offA[NN];
__device__ int g_degA[NN];
__device__ int g_eix[EE];

// ---------------- PTX helpers ----------------
__device__ __forceinline__ uint32_t smem_u32(const void* p) {
    uint32_t a;
    asm("{ .reg .u64 t; cvta.to.shared.u64 t, %1; cvt.u32.u64 %0, t; }" : "=r"(a) : "l"(p));
    return a;
}
__device__ __forceinline__ void cp16(uint32_t saddr, const void* gptr) {
    asm volatile("cp.async.cg.shared.global [%0], [%1], 16;" :: "r"(saddr), "l"(gptr));
}
__device__ __forceinline__ void cp_commit() { asm volatile("cp.async.commit_group;"); }
__device__ __forceinline__ void cp_wait2() { asm volatile("cp.async.wait_group 2;"); }
__device__ __forceinline__ void cp_wait1() { asm volatile("cp.async.wait_group 1;"); }
__device__ __forceinline__ void cp_wait0() { asm volatile("cp.async.wait_group 0;"); }
__device__ __forceinline__ void ldm_x4(uint32_t* r, uint32_t addr) {
    asm volatile("ldmatrix.sync.aligned.m8n8.x4.shared.b16 {%0,%1,%2,%3}, [%4];"
                 : "=r"(r[0]), "=r"(r[1]), "=r"(r[2]), "=r"(r[3]) : "r"(addr));
}
__device__ __forceinline__ void mma_f16(float* c, const uint32_t* a, const uint32_t* b) {
    asm volatile(
        "mma.sync.aligned.m16n8k16.row.col.f32.f16.f16.f32 "
        "{%0,%1,%2,%3}, {%4,%5,%6,%7}, {%8,%9}, {%0,%1,%2,%3};"
        : "+f"(c[0]), "+f"(c[1]), "+f"(c[2]), "+f"(c[3])
        : "r"(a[0]), "r"(a[1]), "r"(a[2]), "r"(a[3]), "r"(b[0]), "r"(b[1]));
}

// ---------------- single-pass fp16 HMMA GEMM (R14/R15 config, unchanged) ----------------
#define GM 128
#define GN 128
#define GK 32
#define KCH (H/GK)       // 24
#define NSTG 4
#define ST_SZ 16384
#define OFF_A 0
#define OFF_B 8192
#define TC_SMEM (NSTG*ST_SZ)   // 64KB

__global__ __launch_bounds__(256, 2) void hmma_gemm(
    const __half* __restrict__ Ah, const __half* __restrict__ Wh,
    const float* __restrict__ bias, __half* __restrict__ C)
{
    extern __shared__ char smem[];
    const uint32_t sb = smem_u32(smem);
    const int tid = threadIdx.x;
    const int wid = tid >> 5, lane = tid & 31;
    const int wm = wid >> 2, wn = wid & 3;
    const int m0 = blockIdx.y * GM, n0 = blockIdx.x * GN;

    const char* aP = (const char*)(Ah + (size_t)m0 * H);
    const char* bP = (const char*)(Wh + (size_t)n0 * H);

    float acc[4][4][4];
    #pragma unroll
    for (int i = 0; i < 4; i++)
        #pragma unroll
        for (int j = 0; j < 4; j++)
            #pragma unroll
            for (int q = 0; q < 4; q++) acc[i][j][q] = 0.f;

    auto load_stage = [&](int stage, int chunk) {
        uint32_t st = sb + stage * ST_SZ;
        int kb = chunk * 64;
        #pragma unroll
        for (int i = 0; i < 4; i++) {
            int buf = i >> 1;
            int rem = ((i & 1) << 8) + tid;
            int row = rem >> 2, ch = rem & 3;
            uint32_t off = (uint32_t)buf * 8192 + row * 64 + (((ch ^ ((row >> 1) & 3))) << 4);
            const char* base = (buf == 0) ? aP : bP;
            cp16(st + off, base + (size_t)row * (H*2) + kb + ch * 16);
        }
        cp_commit();
    };

    load_stage(0, 0);
    load_stage(1, 1);
    load_stage(2, 2);

    const int arow = lane & 15;
    const int akh  = lane >> 4;
    const int bgrp = lane >> 3;
    const int brow8 = lane & 7;

    for (int c = 0; c < KCH; c++) {
        if (c < KCH-2) cp_wait2(); else if (c == KCH-2) cp_wait1(); else cp_wait0();
        __syncthreads();
        if (c + 3 < KCH) load_stage((c + 3) % NSTG, c + 3);

        uint32_t st = sb + (c % NSTG) * ST_SZ;
        #pragma unroll
        for (int j = 0; j < 2; j++) {
            uint32_t ah[4][4];
            int ka = j * 2 + akh;
            #pragma unroll
            for (int mt = 0; mt < 4; mt++) {
                int row = wm * 64 + mt * 16 + arow;
                uint32_t off = row * 64 + ((ka ^ ((row >> 1) & 3)) << 4);
                ldm_x4(ah[mt], st + OFF_A + off);
            }
            #pragma unroll
            for (int ntp = 0; ntp < 4; ntp += 2) {
                uint32_t bq[4];
                int row = wn * 32 + (ntp + (bgrp >> 1)) * 8 + brow8;
                int ch = j * 2 + (bgrp & 1);
                uint32_t off = row * 64 + ((ch ^ ((row >> 1) & 3)) << 4);
                ldm_x4(bq, st + OFF_B + off);
                #pragma unroll
                for (int mt = 0; mt < 4; mt++) {
                    mma_f16(acc[mt][ntp],     ah[mt], bq);
                    mma_f16(acc[mt][ntp + 1], ah[mt], bq + 2);
                }
            }
        }
    }

    const int g = lane >> 2, tq = lane & 3;
    #pragma unroll
    for (int mt = 0; mt < 4; mt++) {
        #pragma unroll
        for (int nt = 0; nt < 4; nt++) {
            int row = m0 + wm*64 + mt*16 + g;
            int col = n0 + wn*32 + nt*8 + tq*2;
            float b0 = bias[col], b1 = bias[col + 1];
            __half2 v0 = __floats2half2_rn(acc[mt][nt][0] + b0, acc[mt][nt][1] + b1);
            __half2 v1 = __floats2half2_rn(acc[mt][nt][2] + b0, acc[mt][nt][3] + b1);
            *(__half2*)&C[(size_t)row * NH2 + col] = v0;
            *(__half2*)&C[(size_t)(row + 8) * NH2 + col] = v1;
        }
    }
}

// ---------------- conversions ----------------
__global__ void k_halfA(const float* __restrict__ in, __half* __restrict__ o, int n)
{
    int i = blockIdx.x * blockDim.x + threadIdx.x;
    if (i < n) o[i] = __float2half_rn(in[i]);
}

__global__ void k_halfWT2(const float* __restrict__ Ws, const float* __restrict__ Wd,
                          const float* __restrict__ bs, const float* __restrict__ bd,
                          __half* __restrict__ WT, float* __restrict__ b2)
{
    __shared__ float tile[32][33];
    int bx = blockIdx.x;
    const int half_nb = HH/32;
    const bool isSrc = (bx < half_nb);
    const float* W = isSrc ? Ws : Wd;
    int rowoff = isSrc ? 0 : HH;
    int n0 = (isSrc ? bx : bx - half_nb) * 32;
    int k0 = blockIdx.y * 32;
    int tx = threadIdx.x, ty = threadIdx.y;
    if (blockIdx.y == 0 && ty == 0)
        b2[rowoff + n0 + tx] = isSrc ? bs[n0 + tx] : bd[n0 + tx];
    #pragma unroll
    for (int i = ty; i < 32; i += 8)
        tile[i][tx] = W[(size_t)(k0 + i) * HH + n0 + tx];
    __syncthreads();
    #pragma unroll
    for (int i = ty; i < 32; i += 8)
        WT[(size_t)(rowoff + n0 + i) * H + k0 + tx] = __float2half_rn(tile[tx][i]);
}

// ---------------- CSR build ----------------
__global__ void k_csr(const int* __restrict__ dst, int* __restrict__ offA,
                      int* __restrict__ degA, int* __restrict__ eix)
{
    __shared__ int cnt[NPG];
    __shared__ int basep[NPG];
    int g = blockIdx.x, tid = threadIdx.x;
    if (tid < NPG) cnt[tid] = 0;
    __syncthreads();
    if (tid < EPG) {
        int e = g * EPG + tid;
        atomicAdd(&cnt[dst[e] - g * NPG], 1);
    }
    __syncthreads();
    if (tid == 0) {
        int run = g * EPG;
        for (int i = 0; i < NPG; i++) {
            basep[i] = run;
            offA[g * NPG + i] = run;
            degA[g * NPG + i] = cnt[i];
            run += cnt[i];
        }
        for (int j = 0; j < EPG; j++) {
            int e = g * EPG + j;
            int dl = dst[e] - g * NPG;
            eix[basep[dl]++] = e;
        }
    }
}

// ---------------- edge kernels ----------------
#define LOG_GRID 4736
__global__ __launch_bounds__(256) void k_logits(const __half* __restrict__ f,
                                                const float* __restrict__ attn_a,
                                                const int* __restrict__ src,
                                                const int* __restrict__ dst,
                                                float* __restrict__ logits)
{
    int h = threadIdx.x >> 5;
    int lane = threadIdx.x & 31;
    const float4* pa = (const float4*)(attn_a + h*H);
    for (int e = blockIdx.x; e < EE; e += LOG_GRID) {
        int s = src[e], d = dst[e];
        const float4* pf = (const float4*)(f + (size_t)s*NH2 + h*H);
        const float4* pd = (const float4*)(f + (size_t)d*NH2 + HH + h*H);
        float acc = 0.f;
        #pragma unroll
        for (int i = lane; i < H/8; i += 32) {
            float4 araw = pf[i];
            float4 braw = pd[i];
            float4 w0 = pa[2*i], w1 = pa[2*i + 1];
            const __half2* ah2 = (const __half2*)&araw;
            const __half2* bh2 = (const __half2*)&braw;
            float wbuf[8] = { w0.x, w0.y, w0.z, w0.w, w1.x, w1.y, w1.z, w1.w };
            #pragma unroll
            for (int q = 0; q < 4; q++) {
                float2 a = __half22float2(ah2[q]);
                float2 b = __half22float2(bh2[q]);
                float v;
                v = a.x + b.x; v = v > 0.f ? v : 0.2f*v; acc += v * wbuf[2*q];
                v = a.y + b.y; v = v > 0.f ? v : 0.2f*v; acc += v * wbuf[2*q + 1];
            }
        }
        #pragma unroll
        for (int o = 16; o; o >>= 1) acc += __shfl_xor_sync(0xffffffffu, acc, o);
        if (lane == 0) logits[e*HEADS + h] = acc;
    }
}

// fused softmax + aggregate + attn_out + GRU-input, block per node
__global__ __launch_bounds__(256) void k_softagg(const float* __restrict__ logits,
                                                 const __half* __restrict__ f,
                                                 const int* __restrict__ src,
                                                 const int* __restrict__ offA,
                                                 const int* __restrict__ degA,
                                                 const int* __restrict__ eix,
                                                 __half* __restrict__ ah,
                                                 float* __restrict__ x,
                                                 float* __restrict__ attn_out)
{
    __shared__ float coef[96*HEADS];   // att * 0.125
    __shared__ int   srcs[96];
    int n = blockIdx.x, tid = threadIdx.x;
    int wid = tid >> 5, lane = tid & 31;
    int off = offA[n], deg = degA[n];
    int g = n / NPG, nl = n - g * NPG;
    bool isVirt = (nl == NPG - 1);

    if (tid < deg) srcs[tid] = src[eix[off + tid]];

    // softmax: warp wid handles head wid over all deg edges
    {
        int h = wid;
        float m = -1e30f;
        for (int j = lane; j < deg; j += 32)
            m = fmaxf(m, logits[eix[off + j]*HEADS + h]);
        #pragma unroll
        for (int o = 16; o; o >>= 1) m = fmaxf(m, __shfl_xor_sync(0xffffffffu, m, o));
        float s = 0.f;
        for (int j = lane; j < deg; j += 32)
            s += expf(logits[eix[off + j]*HEADS + h] - m);
        #pragma unroll
        for (int o = 16; o; o >>= 1) s += __shfl_xor_sync(0xffffffffu, s, o);
        float inv = 0.125f / s;
        for (int j = lane; j < deg; j += 32)
            coef[j*HEADS + h] = expf(logits[eix[off + j]*HEADS + h] - m) * inv;
    }
    __syncthreads();

    if (isVirt) {
        for (int j = tid; j < deg; j += 256) {
            float sm = 0.f;
            #pragma unroll
            for (int h = 0; h < HEADS; h++) sm += coef[j*HEADS + h];
            attn_out[g*N_ATOM + j] = sm;     // == mean_h att
        }
    }

    #pragma unroll
    for (int i2 = tid; i2 < H/2; i2 += 256) {
        float vx = 0.f, vy = 0.f;
        for (int j = 0; j < deg; j++) {
            const __half2* p2 = (const __half2*)(f + (size_t)srcs[j]*NH2) + i2;
            const float* cj = coef + j*HEADS;
            #pragma unroll
            for (int h = 0; h < HEADS; h++) {
                float2 pv = __half22float2(p2[h*(H/2)]);
                vx += cj[h] * pv.x;
                vy += cj[h] * pv.y;
            }
        }
        size_t o2 = (size_t)n*(H/2) + i2;
        ((__half2*)ah)[o2] = __floats2half2_rn(vx, vy);
        if (isVirt) ((float2*)x)[g*(H/2) + i2] = make_float2(vx, vy);
    }
}

// ---------------- batched NT SGEMM for GRU: 64x64 tiles, 144 blocks ----------------
#define BM2 64
#define BN2 64
#define BK2 16
__global__ __launch_bounds__(256) void sgemm_nt2(
    const float* __restrict__ A0, const float* __restrict__ W0, const float* __restrict__ b0,
    float* __restrict__ C0,
    const float* __restrict__ A1, const float* __restrict__ W1, const float* __restrict__ b1,
    float* __restrict__ C1,
    int M, int N, int K)
{
    __shared__ float As[BK2][BM2+1];
    __shared__ float Bs[BK2][BN2+1];
    const float* A    = blockIdx.z ? A1 : A0;
    const float* W    = blockIdx.z ? W1 : W0;
    const float* bias = blockIdx.z ? b1 : b0;
    float*       C    = blockIdx.z ? C1 : C0;
    const int bx = blockIdx.x, by = blockIdx.y;
    const int tid = threadIdx.x;
    const int tx = tid & 15, ty = tid >> 4;
    const float* Ap = A + (size_t)by*BM2*K;
    const float* Wp = W + (size_t)bx*BN2*K;
    const int lr = tid >> 2;
    const int lc = (tid & 3) * 4;
    float acc[4][4];
    #pragma unroll
    for (int i = 0; i < 4; i++)
        #pragma unroll
        for (int j = 0; j < 4; j++) acc[i][j] = 0.f;
    for (int k0 = 0; k0 < K; k0 += BK2) {
        float4 av = *(const float4*)(Ap + (size_t)lr*K + k0 + lc);
        As[lc+0][lr] = av.x; As[lc+1][lr] = av.y;
        As[lc+2][lr] = av.z; As[lc+3][lr] = av.w;
        float4 wv = *(const float4*)(Wp + (size_t)lr*K + k0 + lc);
        Bs[lc+0][lr] = wv.x; Bs[lc+1][lr] = wv.y;
        Bs[lc+2][lr] = wv.z; Bs[lc+3][lr] = wv.w;
        __syncthreads();
        #pragma unroll
        for (int k = 0; k < BK2; k++) {
            float a[4], b[4];
            #pragma unroll
            for (int i = 0; i < 4; i++) a[i] = As[k][ty*4 + i];
            #pragma unroll
            for (int j = 0; j < 4; j++) b[j] = Bs[k][tx*4 + j];
            #pragma unroll
            for (int i = 0; i < 4; i++)
                #pragma unroll
                for (int j = 0; j < 4; j++)
                    acc[i][j] += a[i] * b[j];
        }
        __syncthreads();
    }
    #pragma unroll
    for (int i = 0; i < 4; i++) {
        int row = by*BM2 + ty*4 + i;
        #pragma unroll
        for (int j = 0; j < 4; j++) {
            int col = bx*BN2 + tx*4 + j;
            C[(size_t)row*N + col] = acc[i][j] + bias[col];
        }
    }
}

__global__ void k_gru(const float* __restrict__ gi, const float* __restrict__ gh,
                      const float* __restrict__ hprev, float* __restrict__ mol,
                      float* __restrict__ out_final)
{
    int i = blockIdx.x*blockDim.x + threadIdx.x;
    if (i >= B*H) return;
    int b = i / H, d = i - b*H;
    float ir = gi[b*G3H + d],       hr = gh[b*G3H + d];
    float iz = gi[b*G3H + H + d],   hz = gh[b*G3H + H + d];
    float in_= gi[b*G3H + 2*H + d], hn = gh[b*G3H + 2*H + d];
    float r = 1.f / (1.f + expf(-(ir + hr)));
    float z = 1.f / (1.f + expf(-(iz + hz)));
    float n = tanhf(in_ + r * hn);
    float hp = hprev[i];
    float v = (1.f - z) * n + z * hp;
    v = v > 0.f ? v : 0.f;
    mol[i] = v;
    if (out_final) out_final[i] = v;
}

// ---------------- host ----------------
extern "C" void kernel_launch(void* const* d_in, const int* in_sizes, int n_in,
                              void* d_out, int out_size)
{
    const float* h_nodes  = (const float*)d_in[0];
    const float* mol_feat = (const float*)d_in[1];
    const float* W_src    = (const float*)d_in[2];
    const float* b_src    = (const float*)d_in[3];
    const float* W_dst    = (const float*)d_in[4];
    const float* b_dst    = (const float*)d_in[5];
    const float* attn_a   = (const float*)d_in[6];
    const float* W_ih     = (const float*)d_in[7];
    const float* W_hh     = (const float*)d_in[8];
    const float* b_ih     = (const float*)d_in[9];
    const float* b_hh     = (const float*)d_in[10];
    const int*   src      = (const int*)d_in[11];
    const int*   dst      = (const int*)d_in[12];
    const int*   vnids    = (const int*)d_in[13];  (void)vnids;
    const int*   eids     = (const int*)d_in[14];  (void)eids;
    float* out = (float*)d_out;

    float *logits, *mol, *x, *gi, *gh, *bias2;
    __half *f, *ah, *wh;
    int *offA, *degA, *eixp;
    cudaGetSymbolAddress((void**)&f,      g_f);
    cudaGetSymbolAddress((void**)&logits, g_logits);
    cudaGetSymbolAddress((void**)&mol,    g_mol);
    cudaGetSymbolAddress((void**)&x,      g_x);
    cudaGetSymbolAddress((void**)&gi,     g_gi);
    cudaGetSymbolAddress((void**)&gh,     g_gh);
    cudaGetSymbolAddress((void**)&bias2,  g_bias2);
    cudaGetSymbolAddress((void**)&ah,     g_ah);
    cudaGetSymbolAddress((void**)&wh,     g_wh);
    cudaGetSymbolAddress((void**)&offA,   g_offA);
    cudaGetSymbolAddress((void**)&degA,   g_degA);
    cudaGetSymbolAddress((void**)&eixp,   g_eix);

    cudaFuncSetAttribute(hmma_gemm, cudaFuncAttributeMaxDynamicSharedMemorySize, TC_SMEM);

    static cudaStream_t s2 = nullptr;
    static cudaEvent_t evFork, evW[T_STEPS], evA[T_STEPS], evG[T_STEPS];
    if (!s2) {
        cudaStreamCreateWithFlags(&s2, cudaStreamNonBlocking);
        cudaEventCreateWithFlags(&evFork, cudaEventDisableTiming);
        for (int t = 0; t < T_STEPS; t++) {
            cudaEventCreateWithFlags(&evW[t], cudaEventDisableTiming);
            cudaEventCreateWithFlags(&evA[t], cudaEventDisableTiming);
            cudaEventCreateWithFlags(&evG[t], cudaEventDisableTiming);
        }
    }

    // fork: weight+bias conversions for ALL steps on s2
    cudaEventRecord(evFork, 0);
    cudaStreamWaitEvent(s2, evFork, 0);
    for (int t = 0; t < T_STEPS; t++) {
        k_halfWT2<<<dim3(2*HH/32, H/32), dim3(32, 8), 0, s2>>>(
            W_src + (size_t)t*H*HH, W_dst + (size_t)t*H*HH,
            b_src + t*HH, b_dst + t*HH,
            wh + (size_t)t*NH2*H, bias2 + t*NH2);
        cudaEventRecord(evW[t], s2);
    }

    k_csr<<<B, 160>>>(dst, offA, degA, eixp);
    k_halfA<<<(NN*H + 255)/256, 256>>>(h_nodes, ah, NN*H);

    for (int t = 0; t < T_STEPS; t++) {
        float* xt = x + (t & 1) * (B*H);
        cudaStreamWaitEvent(0, evW[t], 0);

        dim3 gg(NH2/GN, NN/GM);   // 96 x 49
        hmma_gemm<<<gg, 256, TC_SMEM>>>(ah, wh + (size_t)t*NH2*H, bias2 + t*NH2, f);

        k_logits<<<LOG_GRID, 256>>>(f, attn_a + (size_t)t*HEADS*H, src, dst, logits);
        k_softagg<<<NN, 256>>>(logits, f, src, offA, degA, eixp, ah, xt,
                               out + B*H + t*B*N_ATOM);
        cudaEventRecord(evA[t], 0);

        // GRU chain on s2, overlapping next step's GEMM on the main stream
        cudaStreamWaitEvent(s2, evA[t], 0);
        const float* hprev = (t == 0) ? mol_feat : mol;
        sgemm_nt2<<<dim3(G3H/BN2, B/BM2, 2), 256, 0, s2>>>(
            xt,    W_ih + (size_t)t*G3H*H, b_ih + t*G3H, gi,
            hprev, W_hh + (size_t)t*G3H*H, b_hh + t*G3H, gh,
            B, G3H, H);
        k_gru<<<(B*H + 255)/256, 256, 0, s2>>>(gi, gh, hprev, mol,
                                               (t == T_STEPS-1) ? out : nullptr);
        cudaEventRecord(evG[t], s2);
    }
    // join s2 so the captured graph's sink depends on the final GRU output
    cudaStreamWaitEvent(0, evG[T_STEPS-1], 0);
}